// round 5
// baseline (speedup 1.0000x reference)
#include <cuda_runtime.h>
#include <cuda_bf16.h>
#include <cstdint>
#include <math.h>

#define SEQ 2048
#define DM  1024
#define NH  16
#define DK  64

// ---------------- scratch (device globals; no allocation allowed) ----------
__device__ float g_Q[SEQ * DM];
__device__ float g_K[SEQ * DM];
__device__ float g_V[SEQ * DM];
// split inputs
__device__ __nv_bfloat16 g_qh[SEQ * DM], g_ql[SEQ * DM];
__device__ __nv_bfloat16 g_kh[SEQ * DM], g_kl[SEQ * DM];
__device__ __nv_bfloat16 g_vh[SEQ * DM], g_vl[SEQ * DM];
// split weights
__device__ __nv_bfloat16 g_wqh[DM * DM], g_wql[DM * DM];
__device__ __nv_bfloat16 g_wkh[DM * DM], g_wkl[DM * DM];
__device__ __nv_bfloat16 g_wvh[DM * DM], g_wvl[DM * DM];
__device__ __nv_bfloat16 g_woh[DM * DM], g_wol[DM * DM];
// split post-RoPE Q/K, split V, split ctx
__device__ __nv_bfloat16 g_Qh[SEQ * DM], g_Ql[SEQ * DM];
__device__ __nv_bfloat16 g_Kh[SEQ * DM], g_Kl[SEQ * DM];
__device__ __nv_bfloat16 g_Vh[SEQ * DM], g_Vl[SEQ * DM];
__device__ __nv_bfloat16 g_Ch[SEQ * DM], g_Cl[SEQ * DM];

// ---------------------------------------------------------------------------
__device__ __forceinline__ uint32_t pack2_rn(float x0, float x1) {
    uint32_t r;
    asm("cvt.rn.bf16x2.f32 %0, %1, %2;" : "=r"(r) : "f"(x1), "f"(x0));
    return r;
}
__device__ __forceinline__ void cvt_split(float x0, float x1,
                                          uint32_t& ph, uint32_t& pl) {
    ph = pack2_rn(x0, x1);
    float h0 = __uint_as_float(ph << 16);
    float h1 = __uint_as_float(ph & 0xFFFF0000u);
    pl = pack2_rn(x0 - h0, x1 - h1);
}
__device__ __forceinline__ void mma16816(float* c, uint32_t a0, uint32_t a1,
                                         uint32_t a2, uint32_t a3,
                                         uint32_t b0, uint32_t b1) {
    asm volatile(
        "mma.sync.aligned.m16n8k16.row.col.f32.bf16.bf16.f32 "
        "{%0,%1,%2,%3},{%4,%5,%6,%7},{%8,%9},{%0,%1,%2,%3};"
        : "+f"(c[0]), "+f"(c[1]), "+f"(c[2]), "+f"(c[3])
        : "r"(a0), "r"(a1), "r"(a2), "r"(a3), "r"(b0), "r"(b1));
}

// ---------------------------------------------------------------------------
// Split-bf16 GEMM. Block tile 128x64, BK=16, 256 threads (8 warps, 32x32 warp
// tile), double-buffered SMEM with interleaved (hi,lo) uint2 elements.
//   NT=true : C = alpha * A[M,K] * B[N,K]^T ; NT=false: C = alpha*A[M,K]*B[K,N]
//   AFP32   : A operand is fp32 (converted in loader); else pre-split bf16
//   CSPLIT  : write C as split bf16 planes Ch/Cl (alpha/bias ignored)
// Strides are in elements; blockIdx.z batches via sAz/sBz/sCz.
// ---------------------------------------------------------------------------
#define PA2 132   // As pitch in uint2 (132 % 16 == 4 -> phase-conflict-free LDS.64)
#define PB2 68    // Bs pitch in uint2 (68 % 16 == 4)

template <bool NT, bool AFP32, bool CSPLIT, bool HB>
__global__ __launch_bounds__(256, 2)
void gemm_bf16s(const void* __restrict__ Ah_, const void* __restrict__ Al_,
                const __nv_bfloat16* __restrict__ Bh,
                const __nv_bfloat16* __restrict__ Bl,
                float* __restrict__ C,
                __nv_bfloat16* __restrict__ Ch, __nv_bfloat16* __restrict__ Cl,
                int K, int lda, int ldb, int ldc,
                float alpha, const float* __restrict__ bias,
                long long sAz, long long sBz, long long sCz)
{
    __shared__ uint2 As[2][8 * PA2];
    __shared__ uint2 Bs[2][8 * PB2];

    const int t    = threadIdx.x;
    const int lane = t & 31, w = t >> 5;
    const int wm = w & 3;            // M warp (x32 rows)
    const int wn = w >> 2;           // N warp (x32 cols)
    const int grp = lane >> 2, qid = lane & 3;

    const int lm  = t >> 1;          // loader row 0..127
    const int lkp = t & 1;           // k half (0/1 -> k offset 0/8)

    // --- A pointers ---
    const float* Af = nullptr;
    const __nv_bfloat16 *Aph = nullptr, *Apl = nullptr;
    {
        long long rowoff = (long long)(blockIdx.y * 128 + lm) * lda + lkp * 8
                         + (long long)blockIdx.z * sAz;
        if (AFP32) Af = (const float*)Ah_ + rowoff;
        else { Aph = (const __nv_bfloat16*)Ah_ + rowoff;
               Apl = (const __nv_bfloat16*)Al_ + rowoff; }
    }

    // --- B pointers ---
    const __nv_bfloat16 *Bph = nullptr, *Bpl = nullptr;
    int bk2 = 0, bn = 0;
    if (NT) {
        long long off = (long long)(blockIdx.x * 64 + lm) * ldb + lkp * 8
                      + (long long)blockIdx.z * sBz;
        Bph = Bh + off; Bpl = Bl + off;
    } else {
        bk2 = t & 7;                 // k-pair 0..7
        bn  = ((t >> 3) & 15) * 4;   // col 0..60 step 4 (t<128)
        long long off = (long long)(2 * bk2) * ldb + blockIdx.x * 64 + bn
                      + (long long)blockIdx.z * sBz;
        Bph = Bh + off; Bpl = Bl + off;
    }

    float acc[2][4][4];
#pragma unroll
    for (int i = 0; i < 2; i++)
#pragma unroll
        for (int j = 0; j < 4; j++)
#pragma unroll
            for (int r = 0; r < 4; r++) acc[i][j][r] = 0.f;

    // staging registers
    uint32_t ahw[4], alw[4], bhw[4], blw[4];
    float xa[8];

    auto gload = [&](int k0) {
        if (AFP32) {
            *(float4*)&xa[0] = *(const float4*)(Af + k0);
            *(float4*)&xa[4] = *(const float4*)(Af + k0 + 4);
        } else {
            uint4 h = *(const uint4*)(Aph + k0);
            uint4 l = *(const uint4*)(Apl + k0);
            ahw[0] = h.x; ahw[1] = h.y; ahw[2] = h.z; ahw[3] = h.w;
            alw[0] = l.x; alw[1] = l.y; alw[2] = l.z; alw[3] = l.w;
        }
        if (t < 128) {
            if (NT) {
                uint4 h = *(const uint4*)(Bph + k0);
                uint4 l = *(const uint4*)(Bpl + k0);
                bhw[0] = h.x; bhw[1] = h.y; bhw[2] = h.z; bhw[3] = h.w;
                blw[0] = l.x; blw[1] = l.y; blw[2] = l.z; blw[3] = l.w;
            } else {
                // rows 2*bk2 (+k0), 2*bk2+1 (+k0); 4 cols each
                uint2 h0 = *(const uint2*)(Bph + (long long)k0 * ldb);
                uint2 h1 = *(const uint2*)(Bph + (long long)(k0 + 1) * ldb);
                uint2 l0 = *(const uint2*)(Bpl + (long long)k0 * ldb);
                uint2 l1 = *(const uint2*)(Bpl + (long long)(k0 + 1) * ldb);
                // pack k-pairs per column via byte_perm
                bhw[0] = __byte_perm(h0.x, h1.x, 0x5410);
                bhw[1] = __byte_perm(h0.x, h1.x, 0x7632);
                bhw[2] = __byte_perm(h0.y, h1.y, 0x5410);
                bhw[3] = __byte_perm(h0.y, h1.y, 0x7632);
                blw[0] = __byte_perm(l0.x, l1.x, 0x5410);
                blw[1] = __byte_perm(l0.x, l1.x, 0x7632);
                blw[2] = __byte_perm(l0.y, l1.y, 0x5410);
                blw[3] = __byte_perm(l0.y, l1.y, 0x7632);
            }
        }
    };

    auto stage = [&](int buf) {
        if (AFP32) {
#pragma unroll
            for (int j = 0; j < 4; j++) {
                uint32_t ph, pl;
                cvt_split(xa[2 * j], xa[2 * j + 1], ph, pl);
                As[buf][(lkp * 4 + j) * PA2 + lm] = make_uint2(ph, pl);
            }
        } else {
#pragma unroll
            for (int j = 0; j < 4; j++)
                As[buf][(lkp * 4 + j) * PA2 + lm] = make_uint2(ahw[j], alw[j]);
        }
        if (t < 128) {
            if (NT) {
#pragma unroll
                for (int j = 0; j < 4; j++)
                    Bs[buf][(lkp * 4 + j) * PB2 + lm] = make_uint2(bhw[j], blw[j]);
            } else {
                uint4 s0 = make_uint4(bhw[0], blw[0], bhw[1], blw[1]);
                uint4 s1 = make_uint4(bhw[2], blw[2], bhw[3], blw[3]);
                *(uint4*)&Bs[buf][bk2 * PB2 + bn]     = s0;
                *(uint4*)&Bs[buf][bk2 * PB2 + bn + 2] = s1;
            }
        }
    };

    gload(0);
    stage(0);
    __syncthreads();

    for (int k0 = 0; k0 < K; k0 += 16) {
        const int buf = (k0 >> 4) & 1;
        const bool nxt = (k0 + 16) < K;
        if (nxt) gload(k0 + 16);

        uint32_t ah[2][4], al[2][4];
        const int rbase = wm * 32 + grp;
#pragma unroll
        for (int mt = 0; mt < 2; mt++) {
            int r0 = rbase + 16 * mt, r1 = r0 + 8;
            uint2 v;
            v = As[buf][qid * PA2 + r0];       ah[mt][0] = v.x; al[mt][0] = v.y;
            v = As[buf][qid * PA2 + r1];       ah[mt][1] = v.x; al[mt][1] = v.y;
            v = As[buf][(qid + 4) * PA2 + r0]; ah[mt][2] = v.x; al[mt][2] = v.y;
            v = As[buf][(qid + 4) * PA2 + r1]; ah[mt][3] = v.x; al[mt][3] = v.y;
        }
        const int cbase = wn * 32 + grp;
#pragma unroll
        for (int nt4 = 0; nt4 < 4; nt4++) {
            int ci = cbase + nt4 * 8;
            uint2 w0 = Bs[buf][qid * PB2 + ci];
            uint2 w1 = Bs[buf][(qid + 4) * PB2 + ci];
#pragma unroll
            for (int mt = 0; mt < 2; mt++) {
                mma16816(acc[mt][nt4], ah[mt][0], ah[mt][1], ah[mt][2], ah[mt][3], w0.x, w1.x);
                mma16816(acc[mt][nt4], ah[mt][0], ah[mt][1], ah[mt][2], ah[mt][3], w0.y, w1.y);
                mma16816(acc[mt][nt4], al[mt][0], al[mt][1], al[mt][2], al[mt][3], w0.x, w1.x);
            }
        }

        if (nxt) stage(buf ^ 1);
        __syncthreads();
    }

    // --- epilogue ---
#pragma unroll
    for (int mt = 0; mt < 2; mt++) {
        int r0 = blockIdx.y * 128 + wm * 32 + 16 * mt + grp;
        int r1 = r0 + 8;
#pragma unroll
        for (int nt4 = 0; nt4 < 4; nt4++) {
            int col = blockIdx.x * 64 + wn * 32 + nt4 * 8 + 2 * qid;
            if (CSPLIT) {
                long long o0 = (long long)r0 * ldc + col + (long long)blockIdx.z * sCz;
                long long o1 = (long long)r1 * ldc + col + (long long)blockIdx.z * sCz;
                uint32_t ph, pl;
                cvt_split(acc[mt][nt4][0], acc[mt][nt4][1], ph, pl);
                *(uint32_t*)(Ch + o0) = ph;
                *(uint32_t*)(Cl + o0) = pl;
                cvt_split(acc[mt][nt4][2], acc[mt][nt4][3], ph, pl);
                *(uint32_t*)(Ch + o1) = ph;
                *(uint32_t*)(Cl + o1) = pl;
            } else {
                float b0 = HB ? bias[col] : 0.f;
                float b1 = HB ? bias[col + 1] : 0.f;
                long long zz = (long long)blockIdx.z * sCz;
                float2 v0 = make_float2(alpha * acc[mt][nt4][0] + b0,
                                        alpha * acc[mt][nt4][1] + b1);
                float2 v1 = make_float2(alpha * acc[mt][nt4][2] + b0,
                                        alpha * acc[mt][nt4][3] + b1);
                *(float2*)&C[(long long)r0 * ldc + col + zz] = v0;
                *(float2*)&C[(long long)r1 * ldc + col + zz] = v1;
            }
        }
    }
}

// ---------------------------------------------------------------------------
// Elementwise fp32 -> (hi,lo) bf16 split, 4 elems/thread
// ---------------------------------------------------------------------------
__global__ void split4_kernel(const float* __restrict__ X,
                              __nv_bfloat16* __restrict__ H,
                              __nv_bfloat16* __restrict__ L, int n4)
{
    int idx = blockIdx.x * blockDim.x + threadIdx.x;
    if (idx >= n4) return;
    float4 x = ((const float4*)X)[idx];
    uint32_t h0, l0, h1, l1;
    cvt_split(x.x, x.y, h0, l0);
    cvt_split(x.z, x.w, h1, l1);
    *(uint2*)(H + 4 * (size_t)idx) = make_uint2(h0, h1);
    *(uint2*)(L + 4 * (size_t)idx) = make_uint2(l0, l1);
}

// ---------------------------------------------------------------------------
// RoPE + split: read fp32 Q/K, rotate, write split bf16 planes
// ---------------------------------------------------------------------------
__device__ __forceinline__ void split_store(__nv_bfloat16* H, __nv_bfloat16* L,
                                            long long i, float x) {
    __nv_bfloat16 hb = __float2bfloat16(x);
    H[i] = hb;
    L[i] = __float2bfloat16(x - __bfloat162float(hb));
}

__global__ void rope_split_kernel(const float* __restrict__ Q,
                                  const float* __restrict__ K,
                                  __nv_bfloat16* __restrict__ Qh, __nv_bfloat16* __restrict__ Ql,
                                  __nv_bfloat16* __restrict__ Kh, __nv_bfloat16* __restrict__ Kl)
{
    int tid = blockIdx.x * blockDim.x + threadIdx.x;
    if (tid >= SEQ * NH * 32) return;
    int i = tid & 31;
    int h = (tid >> 5) & (NH - 1);
    int s = tid >> 9;

    float inv_freq = expf(-0.28782313662425576f * (float)i);
    float angle = (float)s * inv_freq;
    float sn, cs;
    sincosf(angle, &sn, &cs);

    long long base = (long long)s * DM + h * DK + i;
    float q1 = Q[base], q2 = Q[base + 32];
    split_store(Qh, Ql, base,      q1 * cs - q2 * sn);
    split_store(Qh, Ql, base + 32, q2 * cs + q1 * sn);
    float k1 = K[base], k2 = K[base + 32];
    split_store(Kh, Kl, base,      k1 * cs - k2 * sn);
    split_store(Kh, Kl, base + 32, k2 * cs + k1 * sn);
}

// ---------------------------------------------------------------------------
// Row softmax in-place: one block (256 threads) per row of length 2048.
// ---------------------------------------------------------------------------
__global__ __launch_bounds__(256)
void softmax_rows(float* __restrict__ A)
{
    float* p = A + (long long)blockIdx.x * 2048;
    const int t = threadIdx.x;
    const int lane = t & 31, w = t >> 5;

    float v[8];
    float m = -INFINITY;
#pragma unroll
    for (int j = 0; j < 8; j++) { v[j] = p[t + j * 256]; m = fmaxf(m, v[j]); }

    __shared__ float shm[8];
    __shared__ float shs[8];
#pragma unroll
    for (int o = 16; o; o >>= 1) m = fmaxf(m, __shfl_xor_sync(0xffffffffu, m, o));
    if (lane == 0) shm[w] = m;
    __syncthreads();
    float mm = shm[0];
#pragma unroll
    for (int i = 1; i < 8; i++) mm = fmaxf(mm, shm[i]);

    float sum = 0.f;
#pragma unroll
    for (int j = 0; j < 8; j++) { v[j] = expf(v[j] - mm); sum += v[j]; }
#pragma unroll
    for (int o = 16; o; o >>= 1) sum += __shfl_xor_sync(0xffffffffu, sum, o);
    if (lane == 0) shs[w] = sum;
    __syncthreads();
    float tot = 0.f;
#pragma unroll
    for (int i = 0; i < 8; i++) tot += shs[i];
    float inv = 1.0f / tot;
#pragma unroll
    for (int j = 0; j < 8; j++) p[t + j * 256] = v[j] * inv;
}

// ---------------------------------------------------------------------------
extern "C" void kernel_launch(void* const* d_in, const int* in_sizes, int n_in,
                              void* d_out, int out_size)
{
    const float* q  = (const float*)d_in[0];
    const float* k  = (const float*)d_in[1];
    const float* v  = (const float*)d_in[2];
    const float* wq = (const float*)d_in[3];
    const float* wk = (const float*)d_in[4];
    const float* wv = (const float*)d_in[5];
    const float* wo = (const float*)d_in[6];
    const float* bo = (const float*)d_in[7];

    float* out  = (float*)d_out;              // [2048, 1024]
    float* attn = out + (size_t)SEQ * DM;     // [16, 2048, 2048]

    float *pQ, *pK, *pV;
    cudaGetSymbolAddress((void**)&pQ, g_Q);
    cudaGetSymbolAddress((void**)&pK, g_K);
    cudaGetSymbolAddress((void**)&pV, g_V);

    __nv_bfloat16 *qh,*ql,*kh,*kl,*vh,*vl;
    __nv_bfloat16 *wqh,*wql,*wkh,*wkl,*wvh,*wvl,*woh,*wol;
    __nv_bfloat16 *Qh,*Ql,*Kh,*Kl,*Vh,*Vl,*Ch,*Cl;
    cudaGetSymbolAddress((void**)&qh, g_qh);  cudaGetSymbolAddress((void**)&ql, g_ql);
    cudaGetSymbolAddress((void**)&kh, g_kh);  cudaGetSymbolAddress((void**)&kl, g_kl);
    cudaGetSymbolAddress((void**)&vh, g_vh);  cudaGetSymbolAddress((void**)&vl, g_vl);
    cudaGetSymbolAddress((void**)&wqh, g_wqh); cudaGetSymbolAddress((void**)&wql, g_wql);
    cudaGetSymbolAddress((void**)&wkh, g_wkh); cudaGetSymbolAddress((void**)&wkl, g_wkl);
    cudaGetSymbolAddress((void**)&wvh, g_wvh); cudaGetSymbolAddress((void**)&wvl, g_wvl);
    cudaGetSymbolAddress((void**)&woh, g_woh); cudaGetSymbolAddress((void**)&wol, g_wol);
    cudaGetSymbolAddress((void**)&Qh, g_Qh);  cudaGetSymbolAddress((void**)&Ql, g_Ql);
    cudaGetSymbolAddress((void**)&Kh, g_Kh);  cudaGetSymbolAddress((void**)&Kl, g_Kl);
    cudaGetSymbolAddress((void**)&Vh, g_Vh);  cudaGetSymbolAddress((void**)&Vl, g_Vl);
    cudaGetSymbolAddress((void**)&Ch, g_Ch);  cudaGetSymbolAddress((void**)&Cl, g_Cl);

    const int nIn4 = SEQ * DM / 4, nW4 = DM * DM / 4;

    // 0) pre-split inputs + weights
    split4_kernel<<<nIn4 / 256, 256>>>(q, qh, ql, nIn4);
    split4_kernel<<<nIn4 / 256, 256>>>(k, kh, kl, nIn4);
    split4_kernel<<<nIn4 / 256, 256>>>(v, vh, vl, nIn4);
    split4_kernel<<<nW4 / 256, 256>>>(wq, wqh, wql, nW4);
    split4_kernel<<<nW4 / 256, 256>>>(wk, wkh, wkl, nW4);
    split4_kernel<<<nW4 / 256, 256>>>(wv, wvh, wvl, nW4);
    split4_kernel<<<nW4 / 256, 256>>>(wo, woh, wol, nW4);

    // 1) Projections: X @ W^T  (M=2048, N=1024, K=1024) -> fp32
    dim3 gProj(DM / 64, SEQ / 128, 1);
    gemm_bf16s<true, false, false, false><<<gProj, 256>>>(
        qh, ql, wqh, wql, pQ, nullptr, nullptr, DM, DM, DM, DM, 1.f, nullptr, 0, 0, 0);
    gemm_bf16s<true, false, false, false><<<gProj, 256>>>(
        kh, kl, wkh, wkl, pK, nullptr, nullptr, DM, DM, DM, DM, 1.f, nullptr, 0, 0, 0);
    gemm_bf16s<true, false, false, false><<<gProj, 256>>>(
        vh, vl, wvh, wvl, pV, nullptr, nullptr, DM, DM, DM, DM, 1.f, nullptr, 0, 0, 0);

    // 2) RoPE + split Q,K ; split V
    rope_split_kernel<<<(SEQ * NH * 32 + 255) / 256, 256>>>(pQ, pK, Qh, Ql, Kh, Kl);
    split4_kernel<<<nIn4 / 256, 256>>>(pV, Vh, Vl, nIn4);

    // 3) Scores: attn_h = (Q_h @ K_h^T) / 8
    dim3 gScore(SEQ / 64, SEQ / 128, NH);
    gemm_bf16s<true, false, false, false><<<gScore, 256>>>(
        Qh, Ql, Kh, Kl, attn, nullptr, nullptr, DK, DM, DM, SEQ, 0.125f, nullptr,
        DK, DK, (long long)SEQ * SEQ);

    // 4) Softmax rows
    softmax_rows<<<NH * SEQ, 256>>>(attn);

    // 5) ctx_h = attn_h @ V_h -> split ctx planes
    dim3 gAV(1, SEQ / 128, NH);
    gemm_bf16s<false, true, true, false><<<gAV, 256>>>(
        attn, nullptr, Vh, Vl, nullptr, Ch, Cl, SEQ, SEQ, DM, DM, 1.f, nullptr,
        (long long)SEQ * SEQ, DK, DK);

    // 6) out = ctx @ w_o^T + b_o
    dim3 gOut(DM / 64, SEQ / 128, 1);
    gemm_bf16s<true, false, false, true><<<gOut, 256>>>(
        Ch, Cl, woh, wol, out, nullptr, nullptr, DM, DM, DM, DM, 1.f, bo, 0, 0, 0);
}

// round 7
// speedup vs baseline: 2.0991x; 2.0991x over previous
#include <cuda_runtime.h>
#include <cuda_fp16.h>
#include <cstdint>
#include <math.h>

#define SEQ 2048
#define DM  1024
#define NH  16
#define DK  64

// ---------------- scratch (device globals; no allocation allowed) ----------
__device__ float g_Q[SEQ * DM];
__device__ float g_K[SEQ * DM];
__device__ float g_V[SEQ * DM];
// fp16 operands
__device__ __half g_xq[SEQ * DM], g_xk[SEQ * DM], g_xv[SEQ * DM];
__device__ __half g_wq[DM * DM], g_wk[DM * DM], g_wv[DM * DM], g_wo[DM * DM];
__device__ __half g_Qh[SEQ * DM], g_Kh[SEQ * DM];
__device__ __half g_Vt[NH * DK * SEQ];
__device__ __half g_P[(size_t)NH * SEQ * SEQ];
__device__ __half g_ctx[SEQ * DM];

// ---------------------------------------------------------------------------
__device__ __forceinline__ void ldsm4(uint32_t* r, uint32_t a) {
    asm volatile("ldmatrix.sync.aligned.m8n8.x4.shared.b16 {%0,%1,%2,%3}, [%4];"
        : "=r"(r[0]), "=r"(r[1]), "=r"(r[2]), "=r"(r[3]) : "r"(a));
}
__device__ __forceinline__ void mma_f16(float* c, const uint32_t* a,
                                        uint32_t b0, uint32_t b1) {
    asm volatile("mma.sync.aligned.m16n8k16.row.col.f32.f16.f16.f32 "
        "{%0,%1,%2,%3},{%4,%5,%6,%7},{%8,%9},{%0,%1,%2,%3};"
        : "+f"(c[0]), "+f"(c[1]), "+f"(c[2]), "+f"(c[3])
        : "r"(a[0]), "r"(a[1]), "r"(a[2]), "r"(a[3]), "r"(b0), "r"(b1));
}
// swizzled byte offset of 16B granule (r = row, s = 16B-col 0..3, 64B rows)
__device__ __forceinline__ uint32_t swz(int r, int s) {
    return (uint32_t)((r * 4 + ((s + (r >> 1)) & 3)) << 4);
}

// ---------------------------------------------------------------------------
// fp16 NT GEMM via mma.sync + ldmatrix.
// C[M,N] = alpha * A[M,K] * B[N,K]^T (+bias). Block 128x64, BK=32, 8 warps
// (32x32 warp tiles). EPI=0: fp32 C. EPI=1: fp16 Cf.
// blockIdx.z adds element offsets sAz/sBz/sCz.
// ---------------------------------------------------------------------------
template<int EPI, bool HB>
__global__ __launch_bounds__(256)
void gemm_h(const __half* __restrict__ A, const __half* __restrict__ B,
            float* __restrict__ C, __half* __restrict__ Cf,
            int K, int lda, int ldb, int ldc, float alpha,
            const float* __restrict__ bias,
            long long sAz, long long sBz, long long sCz)
{
    __shared__ __align__(16) __half As[2][128 * 32];
    __shared__ __align__(16) __half Bs[2][64 * 32];

    const int t = threadIdx.x, lane = t & 31, w = t >> 5;
    const int wm = w & 3, wn = w >> 2;
    const int grp = lane >> 2, qid = lane & 3;

    const uint32_t asb0 = (uint32_t)__cvta_generic_to_shared(&As[0][0]);
    const uint32_t asb1 = (uint32_t)__cvta_generic_to_shared(&As[1][0]);
    const uint32_t bsb0 = (uint32_t)__cvta_generic_to_shared(&Bs[0][0]);
    const uint32_t bsb1 = (uint32_t)__cvta_generic_to_shared(&Bs[1][0]);

    // loader indices: granule (r, s): r = t>>2, s = t&3
    const int lr = t >> 2, ls = t & 3;
    const __half* pA0 = A + (long long)blockIdx.z * sAz
                      + (long long)(blockIdx.y * 128 + lr) * lda + ls * 8;
    const __half* pA1 = pA0 + (long long)64 * lda;
    const __half* pB  = B + (long long)blockIdx.z * sBz
                      + (long long)(blockIdx.x * 64 + lr) * ldb + ls * 8;
    const uint32_t dA0 = swz(lr, ls), dA1 = swz(lr + 64, ls), dB = swz(lr, ls);

    float acc[2][4][4];
#pragma unroll
    for (int i = 0; i < 2; i++)
#pragma unroll
        for (int j = 0; j < 4; j++)
#pragma unroll
            for (int r = 0; r < 4; r++) acc[i][j][r] = 0.f;

    uint4 ra0, ra1, rb;
    auto gload = [&](int c) {
        ra0 = *(const uint4*)(pA0 + c * 32);
        ra1 = *(const uint4*)(pA1 + c * 32);
        rb  = *(const uint4*)(pB  + c * 32);
    };
    auto stage = [&](int b) {
        char* ab = (char*)&As[b][0];
        char* bb = (char*)&Bs[b][0];
        *(uint4*)(ab + dA0) = ra0;
        *(uint4*)(ab + dA1) = ra1;
        *(uint4*)(bb + dB)  = rb;
    };

    const int NC = K >> 5;
    gload(0); stage(0);
    __syncthreads();

    for (int c = 0; c < NC; ++c) {
        const int b = c & 1;
        if (c + 1 < NC) gload(c + 1);

        const uint32_t ab = b ? asb1 : asb0;
        const uint32_t bb = b ? bsb1 : bsb0;
#pragma unroll
        for (int ks = 0; ks < 2; ++ks) {
            uint32_t af[2][4], bf[2][4];
#pragma unroll
            for (int mt = 0; mt < 2; ++mt) {
                int r = wm * 32 + mt * 16 + (lane & 15);
                int s = 2 * ks + (lane >> 4);
                ldsm4(af[mt], ab + swz(r, s));
            }
#pragma unroll
            for (int p = 0; p < 2; ++p) {
                int r = wn * 32 + p * 16 + ((lane >> 4) << 3) + (lane & 7);
                int s = 2 * ks + ((lane >> 3) & 1);
                ldsm4(bf[p], bb + swz(r, s));
            }
#pragma unroll
            for (int mt = 0; mt < 2; ++mt)
#pragma unroll
                for (int j = 0; j < 4; ++j)
                    mma_f16(acc[mt][j], af[mt], bf[j >> 1][2 * (j & 1)],
                            bf[j >> 1][2 * (j & 1) + 1]);
        }

        if (c + 1 < NC) stage(b ^ 1);
        __syncthreads();
    }

    // ---- epilogue ----
    const long long zC = (long long)blockIdx.z * sCz;
#pragma unroll
    for (int mt = 0; mt < 2; ++mt) {
        int row0 = blockIdx.y * 128 + wm * 32 + mt * 16 + grp;
#pragma unroll
        for (int j = 0; j < 4; ++j) {
            int col = blockIdx.x * 64 + wn * 32 + j * 8 + 2 * qid;
            if (EPI == 0) {
                float b0 = HB ? bias[col] : 0.f;
                float b1 = HB ? bias[col + 1] : 0.f;
                *(float2*)&C[(long long)row0 * ldc + col + zC] =
                    make_float2(alpha * acc[mt][j][0] + b0, alpha * acc[mt][j][1] + b1);
                *(float2*)&C[(long long)(row0 + 8) * ldc + col + zC] =
                    make_float2(alpha * acc[mt][j][2] + b0, alpha * acc[mt][j][3] + b1);
            } else {
                __half2 v0 = __floats2half2_rn(acc[mt][j][0], acc[mt][j][1]);
                __half2 v1 = __floats2half2_rn(acc[mt][j][2], acc[mt][j][3]);
                *(__half2*)&Cf[(long long)row0 * ldc + col + zC] = v0;
                *(__half2*)&Cf[(long long)(row0 + 8) * ldc + col + zC] = v1;
            }
        }
    }
}

// ---------------------------------------------------------------------------
// fp32 -> fp16 convert, 4 elems/thread
// ---------------------------------------------------------------------------
__global__ void cvt_h(const float* __restrict__ X, __half* __restrict__ H, int n4)
{
    int idx = blockIdx.x * blockDim.x + threadIdx.x;
    if (idx >= n4) return;
    float4 x = ((const float4*)X)[idx];
    __half2 a = __floats2half2_rn(x.x, x.y);
    __half2 b = __floats2half2_rn(x.z, x.w);
    *(uint2*)(H + 4 * (size_t)idx) = make_uint2(*(uint32_t*)&a, *(uint32_t*)&b);
}

// ---------------------------------------------------------------------------
// RoPE: fp32 Q/K -> rotated fp16 planes
// ---------------------------------------------------------------------------
__global__ void rope_h(const float* __restrict__ Q, const float* __restrict__ K,
                       __half* __restrict__ Qh, __half* __restrict__ Kh)
{
    int tid = blockIdx.x * blockDim.x + threadIdx.x;
    if (tid >= SEQ * NH * 32) return;
    int i = tid & 31;
    int h = (tid >> 5) & (NH - 1);
    int s = tid >> 9;

    float inv_freq = expf(-0.28782313662425576f * (float)i);
    float angle = (float)s * inv_freq;
    float sn, cs;
    sincosf(angle, &sn, &cs);

    long long base = (long long)s * DM + h * DK + i;
    float q1 = Q[base], q2 = Q[base + 32];
    Qh[base]      = __float2half_rn(q1 * cs - q2 * sn);
    Qh[base + 32] = __float2half_rn(q2 * cs + q1 * sn);
    float k1 = K[base], k2 = K[base + 32];
    Kh[base]      = __float2half_rn(k1 * cs - k2 * sn);
    Kh[base + 32] = __float2half_rn(k2 * cs + k1 * sn);
}

// ---------------------------------------------------------------------------
// V transpose: fp32 V[s, h*64+d] -> fp16 Vt[h][d][s]
// ---------------------------------------------------------------------------
__global__ void vtrans_h(const float* __restrict__ V, __half* __restrict__ T)
{
    __shared__ float tile[32][33];
    int c0 = blockIdx.x * 32, s0 = blockIdx.y * 32;
    int tx = threadIdx.x, ty = threadIdx.y;   // 32 x 8
#pragma unroll
    for (int k = 0; k < 4; ++k)
        tile[ty + 8 * k][tx] = V[(long long)(s0 + ty + 8 * k) * DM + c0 + tx];
    __syncthreads();
#pragma unroll
    for (int k = 0; k < 4; ++k) {
        int c = c0 + ty + 8 * k;
        int s = s0 + tx;
        long long o = (long long)(c >> 6) * DK * SEQ + (long long)(c & 63) * SEQ + s;
        T[o] = __float2half_rn(tile[tx][ty + 8 * k]);
    }
}

// ---------------------------------------------------------------------------
// Row softmax: fp32 in-place + fp16 plane out
// ---------------------------------------------------------------------------
__global__ __launch_bounds__(256)
void softmax_rows(float* __restrict__ A, __half* __restrict__ H)
{
    float* p = A + (long long)blockIdx.x * 2048;
    __half* ph = H + (long long)blockIdx.x * 2048;
    const int t = threadIdx.x;
    const int lane = t & 31, w = t >> 5;

    float v[8];
    float m = -INFINITY;
#pragma unroll
    for (int j = 0; j < 8; j++) { v[j] = p[t + j * 256]; m = fmaxf(m, v[j]); }

    __shared__ float shm[8];
    __shared__ float shs[8];
#pragma unroll
    for (int o = 16; o; o >>= 1) m = fmaxf(m, __shfl_xor_sync(0xffffffffu, m, o));
    if (lane == 0) shm[w] = m;
    __syncthreads();
    float mm = shm[0];
#pragma unroll
    for (int i = 1; i < 8; i++) mm = fmaxf(mm, shm[i]);

    float sum = 0.f;
#pragma unroll
    for (int j = 0; j < 8; j++) { v[j] = expf(v[j] - mm); sum += v[j]; }
#pragma unroll
    for (int o = 16; o; o >>= 1) sum += __shfl_xor_sync(0xffffffffu, sum, o);
    if (lane == 0) shs[w] = sum;
    __syncthreads();
    float tot = 0.f;
#pragma unroll
    for (int i = 0; i < 8; i++) tot += shs[i];
    float inv = 1.0f / tot;
#pragma unroll
    for (int j = 0; j < 8; j++) {
        float r = v[j] * inv;
        p[t + j * 256] = r;
        ph[t + j * 256] = __float2half_rn(r);
    }
}

// ---------------------------------------------------------------------------
extern "C" void kernel_launch(void* const* d_in, const int* in_sizes, int n_in,
                              void* d_out, int out_size)
{
    const float* q  = (const float*)d_in[0];
    const float* k  = (const float*)d_in[1];
    const float* v  = (const float*)d_in[2];
    const float* wq = (const float*)d_in[3];
    const float* wk = (const float*)d_in[4];
    const float* wv = (const float*)d_in[5];
    const float* wo = (const float*)d_in[6];
    const float* bo = (const float*)d_in[7];

    float* out  = (float*)d_out;              // [2048, 1024]
    float* attn = out + (size_t)SEQ * DM;     // [16, 2048, 2048]

    float *pQ, *pK, *pV;
    cudaGetSymbolAddress((void**)&pQ, g_Q);
    cudaGetSymbolAddress((void**)&pK, g_K);
    cudaGetSymbolAddress((void**)&pV, g_V);

    __half *xq,*xk,*xv,*hwq,*hwk,*hwv,*hwo,*Qh,*Kh,*Vt,*P,*ctx;
    cudaGetSymbolAddress((void**)&xq, g_xq);
    cudaGetSymbolAddress((void**)&xk, g_xk);
    cudaGetSymbolAddress((void**)&xv, g_xv);
    cudaGetSymbolAddress((void**)&hwq, g_wq);
    cudaGetSymbolAddress((void**)&hwk, g_wk);
    cudaGetSymbolAddress((void**)&hwv, g_wv);
    cudaGetSymbolAddress((void**)&hwo, g_wo);
    cudaGetSymbolAddress((void**)&Qh, g_Qh);
    cudaGetSymbolAddress((void**)&Kh, g_Kh);
    cudaGetSymbolAddress((void**)&Vt, g_Vt);
    cudaGetSymbolAddress((void**)&P, g_P);
    cudaGetSymbolAddress((void**)&ctx, g_ctx);

    const int nIn4 = SEQ * DM / 4, nW4 = DM * DM / 4;

    // 0) fp32 -> fp16 operands
    cvt_h<<<nIn4 / 256, 256>>>(q, xq, nIn4);
    cvt_h<<<nIn4 / 256, 256>>>(k, xk, nIn4);
    cvt_h<<<nIn4 / 256, 256>>>(v, xv, nIn4);
    cvt_h<<<nW4 / 256, 256>>>(wq, hwq, nW4);
    cvt_h<<<nW4 / 256, 256>>>(wk, hwk, nW4);
    cvt_h<<<nW4 / 256, 256>>>(wv, hwv, nW4);
    cvt_h<<<nW4 / 256, 256>>>(wo, hwo, nW4);

    // 1) Projections: X @ W^T -> fp32
    dim3 gProj(DM / 64, SEQ / 128, 1);
    gemm_h<0, false><<<gProj, 256>>>(xq, hwq, pQ, nullptr, DM, DM, DM, DM, 1.f, nullptr, 0, 0, 0);
    gemm_h<0, false><<<gProj, 256>>>(xk, hwk, pK, nullptr, DM, DM, DM, DM, 1.f, nullptr, 0, 0, 0);
    gemm_h<0, false><<<gProj, 256>>>(xv, hwv, pV, nullptr, DM, DM, DM, DM, 1.f, nullptr, 0, 0, 0);

    // 2) RoPE -> fp16 Q/K ; V transpose -> fp16 Vt
    rope_h<<<(SEQ * NH * 32 + 255) / 256, 256>>>(pQ, pK, Qh, Kh);
    vtrans_h<<<dim3(DM / 32, SEQ / 32), dim3(32, 8)>>>(pV, Vt);

    // 3) Scores: attn_h = (Q_h @ K_h^T) / 8   (K=64 per head)
    dim3 gScore(SEQ / 64, SEQ / 128, NH);
    gemm_h<0, false><<<gScore, 256>>>(Qh, Kh, attn, nullptr, DK, DM, DM, SEQ, 0.125f,
                                      nullptr, DK, DK, (long long)SEQ * SEQ);

    // 4) Softmax -> fp32 attn + fp16 probs
    softmax_rows<<<NH * SEQ, 256>>>(attn, P);

    // 5) ctx_h = P_h @ Vt_h^T  (M=2048, N=64, K=2048) -> fp16 ctx
    dim3 gAV(1, SEQ / 128, NH);
    gemm_h<1, false><<<gAV, 256>>>(P, Vt, nullptr, ctx, SEQ, SEQ, SEQ, DM, 1.f,
                                   nullptr, (long long)SEQ * SEQ, (long long)DK * SEQ, DK);

    // 6) out = ctx @ w_o^T + b_o
    dim3 gOut(DM / 64, SEQ / 128, 1);
    gemm_h<0, true><<<gOut, 256>>>(ctx, hwo, out, nullptr, DM, DM, DM, DM, 1.f, bo, 0, 0, 0);
}

// round 9
// speedup vs baseline: 2.3936x; 1.1403x over previous
#include <cuda_runtime.h>
#include <cuda_fp16.h>
#include <cstdint>
#include <math.h>

#define SEQ 2048
#define DM  1024
#define NH  16
#define DK  64

// ---------------- scratch (device globals; no allocation allowed) ----------
__device__ float g_Q[SEQ * DM];
__device__ float g_K[SEQ * DM];
__device__ float g_V[SEQ * DM];
__device__ __half g_xq[SEQ * DM], g_xk[SEQ * DM], g_xv[SEQ * DM];
__device__ __half g_wq[DM * DM], g_wk[DM * DM], g_wv[DM * DM], g_wo[DM * DM];
__device__ __half g_Qh[SEQ * DM], g_Kh[SEQ * DM];
__device__ __half g_Vt[NH * DK * SEQ];
__device__ __half g_P[(size_t)NH * SEQ * SEQ];   // scores, then probs
__device__ __half g_ctx[SEQ * DM];

// ---------------------------------------------------------------------------
__device__ __forceinline__ void ldsm4(uint32_t* r, uint32_t a) {
    asm volatile("ldmatrix.sync.aligned.m8n8.x4.shared.b16 {%0,%1,%2,%3}, [%4];"
        : "=r"(r[0]), "=r"(r[1]), "=r"(r[2]), "=r"(r[3]) : "r"(a));
}
__device__ __forceinline__ void mma_f16(float* c, const uint32_t* a,
                                        uint32_t b0, uint32_t b1) {
    asm volatile("mma.sync.aligned.m16n8k16.row.col.f32.f16.f16.f32 "
        "{%0,%1,%2,%3},{%4,%5,%6,%7},{%8,%9},{%0,%1,%2,%3};"
        : "+f"(c[0]), "+f"(c[1]), "+f"(c[2]), "+f"(c[3])
        : "r"(a[0]), "r"(a[1]), "r"(a[2]), "r"(a[3]), "r"(b0), "r"(b1));
}
__device__ __forceinline__ void cp16(uint32_t dst, const void* src) {
    asm volatile("cp.async.cg.shared.global [%0], [%1], 16;" :: "r"(dst), "l"(src));
}
__device__ __forceinline__ void cp_commit() {
    asm volatile("cp.async.commit_group;");
}
template<int N> __device__ __forceinline__ void cp_wait() {
    asm volatile("cp.async.wait_group %0;" :: "n"(N));
}
// swizzled byte offset of 16B granule (r = row, s = 16B-col 0..3, 64B rows)
__device__ __forceinline__ uint32_t swz(int r, int s) {
    return (uint32_t)((r * 4 + ((s + (r >> 1)) & 3)) << 4);
}

// ---------------------------------------------------------------------------
// fp16 NT GEMM, mma.sync + ldmatrix, 3-stage cp.async pipeline.
// C[M,N] = alpha * A[M,K] * B[N,K]^T (+bias). Block 128x64, BK=32, 8 warps.
// EPI=0: fp32 C (+bias). EPI=1: fp16 Cf (alpha applied).
// ---------------------------------------------------------------------------
template<int EPI, bool HB>
__global__ __launch_bounds__(256)
void gemm_h(const __half* __restrict__ A, const __half* __restrict__ B,
            float* __restrict__ C, __half* __restrict__ Cf,
            int K, int lda, int ldb, int ldc, float alpha,
            const float* __restrict__ bias,
            long long sAz, long long sBz, long long sCz)
{
    __shared__ __align__(16) __half As[3][128 * 32];
    __shared__ __align__(16) __half Bs[3][64 * 32];
    constexpr uint32_t ASTR = 128 * 32 * 2, BSTR = 64 * 32 * 2;

    const int t = threadIdx.x, lane = t & 31, w = t >> 5;
    const int wm = w & 3, wn = w >> 2;
    const int grp = lane >> 2, qid = lane & 3;

    const uint32_t asb = (uint32_t)__cvta_generic_to_shared(&As[0][0]);
    const uint32_t bsb = (uint32_t)__cvta_generic_to_shared(&Bs[0][0]);

    const int lr = t >> 2, ls = t & 3;
    const __half* pA0 = A + (long long)blockIdx.z * sAz
                      + (long long)(blockIdx.y * 128 + lr) * lda + ls * 8;
    const __half* pA1 = pA0 + (long long)64 * lda;
    const __half* pB  = B + (long long)blockIdx.z * sBz
                      + (long long)(blockIdx.x * 64 + lr) * ldb + ls * 8;
    const uint32_t dA0 = swz(lr, ls), dA1 = swz(lr + 64, ls), dB = swz(lr, ls);

    auto load_async = [&](int c, int s) {
        cp16(asb + s * ASTR + dA0, pA0 + c * 32);
        cp16(asb + s * ASTR + dA1, pA1 + c * 32);
        cp16(bsb + s * BSTR + dB,  pB  + c * 32);
    };

    float acc[2][4][4];
#pragma unroll
    for (int i = 0; i < 2; i++)
#pragma unroll
        for (int j = 0; j < 4; j++)
#pragma unroll
            for (int r = 0; r < 4; r++) acc[i][j][r] = 0.f;

    const int NC = K >> 5;
    load_async(0, 0); cp_commit();
    if (NC > 1) { load_async(1, 1); cp_commit(); }

    int s_cur = 0;
    for (int c = 0; c < NC; ++c) {
        if (c + 1 < NC) cp_wait<1>(); else cp_wait<0>();
        __syncthreads();

        if (c + 2 < NC) {
            int s2 = s_cur + 2; if (s2 >= 3) s2 -= 3;
            load_async(c + 2, s2);
            cp_commit();
        }

        const uint32_t ab = asb + s_cur * ASTR;
        const uint32_t bb = bsb + s_cur * BSTR;
#pragma unroll
        for (int ks = 0; ks < 2; ++ks) {
            uint32_t af[2][4], bf[2][4];
#pragma unroll
            for (int mt = 0; mt < 2; ++mt) {
                int r = wm * 32 + mt * 16 + (lane & 15);
                int s = 2 * ks + (lane >> 4);
                ldsm4(af[mt], ab + swz(r, s));
            }
#pragma unroll
            for (int p = 0; p < 2; ++p) {
                int r = wn * 32 + p * 16 + ((lane >> 4) << 3) + (lane & 7);
                int s = 2 * ks + ((lane >> 3) & 1);
                ldsm4(bf[p], bb + swz(r, s));
            }
#pragma unroll
            for (int mt = 0; mt < 2; ++mt)
#pragma unroll
                for (int j = 0; j < 4; ++j)
                    mma_f16(acc[mt][j], af[mt], bf[j >> 1][2 * (j & 1)],
                            bf[j >> 1][2 * (j & 1) + 1]);
        }

        ++s_cur; if (s_cur == 3) s_cur = 0;
        __syncthreads();
    }

    // ---- epilogue ----
    const long long zC = (long long)blockIdx.z * sCz;
#pragma unroll
    for (int mt = 0; mt < 2; ++mt) {
        int row0 = blockIdx.y * 128 + wm * 32 + mt * 16 + grp;
#pragma unroll
        for (int j = 0; j < 4; ++j) {
            int col = blockIdx.x * 64 + wn * 32 + j * 8 + 2 * qid;
            if (EPI == 0) {
                float b0 = HB ? bias[col] : 0.f;
                float b1 = HB ? bias[col + 1] : 0.f;
                *(float2*)&C[(long long)row0 * ldc + col + zC] =
                    make_float2(alpha * acc[mt][j][0] + b0, alpha * acc[mt][j][1] + b1);
                *(float2*)&C[(long long)(row0 + 8) * ldc + col + zC] =
                    make_float2(alpha * acc[mt][j][2] + b0, alpha * acc[mt][j][3] + b1);
            } else {
                __half2 v0 = __floats2half2_rn(alpha * acc[mt][j][0], alpha * acc[mt][j][1]);
                __half2 v1 = __floats2half2_rn(alpha * acc[mt][j][2], alpha * acc[mt][j][3]);
                *(__half2*)&Cf[(long long)row0 * ldc + col + zC] = v0;
                *(__half2*)&Cf[(long long)(row0 + 8) * ldc + col + zC] = v1;
            }
        }
    }
}

// ---------------------------------------------------------------------------
// Batched fp32 -> fp16 convert: blockIdx.y selects tensor
// ---------------------------------------------------------------------------
__global__ void cvt_h3(const float* __restrict__ a, const float* __restrict__ b,
                       const float* __restrict__ c,
                       __half* __restrict__ A, __half* __restrict__ B,
                       __half* __restrict__ C, int n4)
{
    int idx = blockIdx.x * blockDim.x + threadIdx.x;
    if (idx >= n4) return;
    const float* src = (blockIdx.y == 0) ? a : (blockIdx.y == 1) ? b : c;
    __half* dst = (blockIdx.y == 0) ? A : (blockIdx.y == 1) ? B : C;
    float4 x = ((const float4*)src)[idx];
    __half2 u = __floats2half2_rn(x.x, x.y);
    __half2 v = __floats2half2_rn(x.z, x.w);
    *(uint2*)(dst + 4 * (size_t)idx) = make_uint2(*(uint32_t*)&u, *(uint32_t*)&v);
}

__global__ void cvt_h4(const float* __restrict__ a, const float* __restrict__ b,
                       const float* __restrict__ c, const float* __restrict__ d,
                       __half* __restrict__ A, __half* __restrict__ B,
                       __half* __restrict__ C, __half* __restrict__ D, int n4)
{
    int idx = blockIdx.x * blockDim.x + threadIdx.x;
    if (idx >= n4) return;
    const float* src = (blockIdx.y == 0) ? a : (blockIdx.y == 1) ? b
                     : (blockIdx.y == 2) ? c : d;
    __half* dst = (blockIdx.y == 0) ? A : (blockIdx.y == 1) ? B
                : (blockIdx.y == 2) ? C : D;
    float4 x = ((const float4*)src)[idx];
    __half2 u = __floats2half2_rn(x.x, x.y);
    __half2 v = __floats2half2_rn(x.z, x.w);
    *(uint2*)(dst + 4 * (size_t)idx) = make_uint2(*(uint32_t*)&u, *(uint32_t*)&v);
}

// ---------------------------------------------------------------------------
// RoPE: fp32 Q/K -> rotated fp16 planes
// ---------------------------------------------------------------------------
__global__ void rope_h(const float* __restrict__ Q, const float* __restrict__ K,
                       __half* __restrict__ Qh, __half* __restrict__ Kh)
{
    int tid = blockIdx.x * blockDim.x + threadIdx.x;
    if (tid >= SEQ * NH * 32) return;
    int i = tid & 31;
    int h = (tid >> 5) & (NH - 1);
    int s = tid >> 9;

    float inv_freq = expf(-0.28782313662425576f * (float)i);
    float angle = (float)s * inv_freq;
    float sn, cs;
    sincosf(angle, &sn, &cs);

    long long base = (long long)s * DM + h * DK + i;
    float q1 = Q[base], q2 = Q[base + 32];
    Qh[base]      = __float2half_rn(q1 * cs - q2 * sn);
    Qh[base + 32] = __float2half_rn(q2 * cs + q1 * sn);
    float k1 = K[base], k2 = K[base + 32];
    Kh[base]      = __float2half_rn(k1 * cs - k2 * sn);
    Kh[base + 32] = __float2half_rn(k2 * cs + k1 * sn);
}

// ---------------------------------------------------------------------------
// V transpose: fp32 V[s, h*64+d] -> fp16 Vt[h][d][s]
// ---------------------------------------------------------------------------
__global__ void vtrans_h(const float* __restrict__ V, __half* __restrict__ T)
{
    __shared__ float tile[32][33];
    int c0 = blockIdx.x * 32, s0 = blockIdx.y * 32;
    int tx = threadIdx.x, ty = threadIdx.y;   // 32 x 8
#pragma unroll
    for (int k = 0; k < 4; ++k)
        tile[ty + 8 * k][tx] = V[(long long)(s0 + ty + 8 * k) * DM + c0 + tx];
    __syncthreads();
#pragma unroll
    for (int k = 0; k < 4; ++k) {
        int c = c0 + ty + 8 * k;
        int s = s0 + tx;
        long long o = (long long)(c >> 6) * DK * SEQ + (long long)(c & 63) * SEQ + s;
        T[o] = __float2half_rn(tile[tx][ty + 8 * k]);
    }
}

// ---------------------------------------------------------------------------
// Softmax: read fp16 scores from P, write fp32 probs to attn and fp16 to P.
// One block (256 threads) per row; 8 contiguous elems per thread.
// ---------------------------------------------------------------------------
__global__ __launch_bounds__(256)
void softmax_h(__half* __restrict__ P, float* __restrict__ attn)
{
    const long long rbase = (long long)blockIdx.x * 2048;
    __half* p = P + rbase;
    float* a = attn + rbase;
    const int t = threadIdx.x;
    const int lane = t & 31, w = t >> 5;

    uint4 raw = *(const uint4*)(p + 8 * t);
    float v[8];
    {
        float2 f0 = __half22float2(*(__half2*)&raw.x);
        float2 f1 = __half22float2(*(__half2*)&raw.y);
        float2 f2 = __half22float2(*(__half2*)&raw.z);
        float2 f3 = __half22float2(*(__half2*)&raw.w);
        v[0] = f0.x; v[1] = f0.y; v[2] = f1.x; v[3] = f1.y;
        v[4] = f2.x; v[5] = f2.y; v[6] = f3.x; v[7] = f3.y;
    }

    float m = v[0];
#pragma unroll
    for (int j = 1; j < 8; j++) m = fmaxf(m, v[j]);

    __shared__ float shm[8], shs[8];
#pragma unroll
    for (int o = 16; o; o >>= 1) m = fmaxf(m, __shfl_xor_sync(0xffffffffu, m, o));
    if (lane == 0) shm[w] = m;
    __syncthreads();
    float mm = shm[0];
#pragma unroll
    for (int i = 1; i < 8; i++) mm = fmaxf(mm, shm[i]);

    float sum = 0.f;
#pragma unroll
    for (int j = 0; j < 8; j++) { v[j] = expf(v[j] - mm); sum += v[j]; }
#pragma unroll
    for (int o = 16; o; o >>= 1) sum += __shfl_xor_sync(0xffffffffu, sum, o);
    if (lane == 0) shs[w] = sum;
    __syncthreads();
    float tot = 0.f;
#pragma unroll
    for (int i = 0; i < 8; i++) tot += shs[i];
    float inv = 1.0f / tot;

    float r[8];
#pragma unroll
    for (int j = 0; j < 8; j++) r[j] = v[j] * inv;

    *(float4*)(a + 8 * t)     = make_float4(r[0], r[1], r[2], r[3]);
    *(float4*)(a + 8 * t + 4) = make_float4(r[4], r[5], r[6], r[7]);
    __half2 h0 = __floats2half2_rn(r[0], r[1]);
    __half2 h1 = __floats2half2_rn(r[2], r[3]);
    __half2 h2 = __floats2half2_rn(r[4], r[5]);
    __half2 h3 = __floats2half2_rn(r[6], r[7]);
    *(uint4*)(p + 8 * t) = make_uint4(*(uint32_t*)&h0, *(uint32_t*)&h1,
                                      *(uint32_t*)&h2, *(uint32_t*)&h3);
}

// ---------------------------------------------------------------------------
extern "C" void kernel_launch(void* const* d_in, const int* in_sizes, int n_in,
                              void* d_out, int out_size)
{
    const float* q  = (const float*)d_in[0];
    const float* k  = (const float*)d_in[1];
    const float* v  = (const float*)d_in[2];
    const float* wq = (const float*)d_in[3];
    const float* wk = (const float*)d_in[4];
    const float* wv = (const float*)d_in[5];
    const float* wo = (const float*)d_in[6];
    const float* bo = (const float*)d_in[7];

    float* out  = (float*)d_out;              // [2048, 1024]
    float* attn = out + (size_t)SEQ * DM;     // [16, 2048, 2048]

    float *pQ, *pK, *pV;
    cudaGetSymbolAddress((void**)&pQ, g_Q);
    cudaGetSymbolAddress((void**)&pK, g_K);
    cudaGetSymbolAddress((void**)&pV, g_V);

    __half *xq,*xk,*xv,*hwq,*hwk,*hwv,*hwo,*Qh,*Kh,*Vt,*P,*ctx;
    cudaGetSymbolAddress((void**)&xq, g_xq);
    cudaGetSymbolAddress((void**)&xk, g_xk);
    cudaGetSymbolAddress((void**)&xv, g_xv);
    cudaGetSymbolAddress((void**)&hwq, g_wq);
    cudaGetSymbolAddress((void**)&hwk, g_wk);
    cudaGetSymbolAddress((void**)&hwv, g_wv);
    cudaGetSymbolAddress((void**)&hwo, g_wo);
    cudaGetSymbolAddress((void**)&Qh, g_Qh);
    cudaGetSymbolAddress((void**)&Kh, g_Kh);
    cudaGetSymbolAddress((void**)&Vt, g_Vt);
    cudaGetSymbolAddress((void**)&P, g_P);
    cudaGetSymbolAddress((void**)&ctx, g_ctx);

    const int nIn4 = SEQ * DM / 4, nW4 = DM * DM / 4;

    // 0) fp32 -> fp16 operands (batched)
    cvt_h3<<<dim3(nIn4 / 256, 3), 256>>>(q, k, v, xq, xk, xv, nIn4);
    cvt_h4<<<dim3(nW4 / 256, 4), 256>>>(wq, wk, wv, wo, hwq, hwk, hwv, hwo, nW4);

    // 1) Projections: X @ W^T -> fp32
    dim3 gProj(DM / 64, SEQ / 128, 1);
    gemm_h<0, false><<<gProj, 256>>>(xq, hwq, pQ, nullptr, DM, DM, DM, DM, 1.f, nullptr, 0, 0, 0);
    gemm_h<0, false><<<gProj, 256>>>(xk, hwk, pK, nullptr, DM, DM, DM, DM, 1.f, nullptr, 0, 0, 0);
    gemm_h<0, false><<<gProj, 256>>>(xv, hwv, pV, nullptr, DM, DM, DM, DM, 1.f, nullptr, 0, 0, 0);

    // 2) RoPE -> fp16 Q/K ; V transpose -> fp16 Vt
    rope_h<<<(SEQ * NH * 32 + 255) / 256, 256>>>(pQ, pK, Qh, Kh);
    vtrans_h<<<dim3(DM / 32, SEQ / 32), dim3(32, 8)>>>(pV, Vt);

    // 3) Scores -> fp16 P = (Q_h @ K_h^T) / 8
    dim3 gScore(SEQ / 64, SEQ / 128, NH);
    gemm_h<1, false><<<gScore, 256>>>(Qh, Kh, nullptr, P, DK, DM, DM, SEQ, 0.125f,
                                      nullptr, DK, DK, (long long)SEQ * SEQ);

    // 4) Softmax: P fp16 -> attn fp32 + P fp16 (probs)
    softmax_h<<<NH * SEQ, 256>>>(P, attn);

    // 5) ctx_h = P_h @ Vt_h^T  (M=2048, N=64, K=2048) -> fp16 ctx
    dim3 gAV(1, SEQ / 128, NH);
    gemm_h<1, false><<<gAV, 256>>>(P, Vt, nullptr, ctx, SEQ, SEQ, SEQ, DM, 1.f,
                                   nullptr, (long long)SEQ * SEQ, (long long)DK * SEQ, DK);

    // 6) out = ctx @ w_o^T + b_o
    dim3 gOut(DM / 64, SEQ / 128, 1);
    gemm_h<0, true><<<gOut, 256>>>(ctx, hwo, out, nullptr, DM, DM, DM, DM, 1.f, bo, 0, 0, 0);
}

// round 10
// speedup vs baseline: 2.3977x; 1.0017x over previous
#include <cuda_runtime.h>
#include <cuda_fp16.h>
#include <cstdint>
#include <math.h>

#define SEQ 2048
#define DM  1024
#define NH  16
#define DK  64

// ---------------- scratch (device globals; no allocation allowed) ----------
__device__ float g_Q[SEQ * DM];
__device__ float g_K[SEQ * DM];
__device__ float g_V[SEQ * DM];
__device__ __half g_xq[SEQ * DM], g_xk[SEQ * DM], g_xv[SEQ * DM];
__device__ __half g_wq[DM * DM], g_wk[DM * DM], g_wv[DM * DM], g_wo[DM * DM];
__device__ __half g_Qh[SEQ * DM], g_Kh[SEQ * DM];
__device__ __half g_Vt[NH * DK * SEQ];
__device__ __half g_P[(size_t)NH * SEQ * SEQ];   // scores, then probs
__device__ __half g_ctx[SEQ * DM];

// ---------------------------------------------------------------------------
__device__ __forceinline__ void ldsm4(uint32_t* r, uint32_t a) {
    asm volatile("ldmatrix.sync.aligned.m8n8.x4.shared.b16 {%0,%1,%2,%3}, [%4];"
        : "=r"(r[0]), "=r"(r[1]), "=r"(r[2]), "=r"(r[3]) : "r"(a));
}
__device__ __forceinline__ void mma_f16(float* c, const uint32_t* a,
                                        uint32_t b0, uint32_t b1) {
    asm volatile("mma.sync.aligned.m16n8k16.row.col.f32.f16.f16.f32 "
        "{%0,%1,%2,%3},{%4,%5,%6,%7},{%8,%9},{%0,%1,%2,%3};"
        : "+f"(c[0]), "+f"(c[1]), "+f"(c[2]), "+f"(c[3])
        : "r"(a[0]), "r"(a[1]), "r"(a[2]), "r"(a[3]), "r"(b0), "r"(b1));
}
__device__ __forceinline__ void cp16(uint32_t dst, const void* src) {
    asm volatile("cp.async.cg.shared.global [%0], [%1], 16;" :: "r"(dst), "l"(src));
}
__device__ __forceinline__ void cp_commit() {
    asm volatile("cp.async.commit_group;");
}
template<int N> __device__ __forceinline__ void cp_wait() {
    asm volatile("cp.async.wait_group %0;" :: "n"(N));
}
// swizzled byte offset of 16B granule (r = row, s = 16B-col 0..3, 64B rows)
__device__ __forceinline__ uint32_t swz(int r, int s) {
    return (uint32_t)((r * 4 + ((s + (r >> 1)) & 3)) << 4);
}

// ---------------------------------------------------------------------------
// fp16 NT GEMM, mma.sync + ldmatrix, 3-stage cp.async pipeline.
// C[M,N] = alpha * A[M,K] * B[N,K]^T (+bias). Block tile 128 x TN (TN=64|128),
// 8 warps: 4 (M) x 2 (N), warp tile 32 x TN/2, BK=32.
// EPI=0: fp32 C (+bias). EPI=1: fp16 Cf (alpha applied).
// ---------------------------------------------------------------------------
template<int TN, int EPI, bool HB>
__global__ __launch_bounds__(256)
void gemm_h(const __half* __restrict__ A, const __half* __restrict__ B,
            float* __restrict__ C, __half* __restrict__ Cf,
            int K, int lda, int ldb, int ldc, float alpha,
            const float* __restrict__ bias,
            long long sAz, long long sBz, long long sCz)
{
    constexpr int NP = TN / 32;            // n16 ldsm tiles per warp (2 or 4)
    constexpr int NJ = TN / 16;            // n8 mma tiles per warp (4 or 8)
    __shared__ __align__(16) __half As[3][128 * 32];
    __shared__ __align__(16) __half Bs[3][TN * 32];
    constexpr uint32_t ASTR = 128 * 32 * 2, BSTR = TN * 32 * 2;

    const int t = threadIdx.x, lane = t & 31, w = t >> 5;
    const int wm = w & 3, wn = w >> 2;
    const int grp = lane >> 2, qid = lane & 3;

    const uint32_t asb = (uint32_t)__cvta_generic_to_shared(&As[0][0]);
    const uint32_t bsb = (uint32_t)__cvta_generic_to_shared(&Bs[0][0]);

    const int lr = t >> 2, ls = t & 3;
    const __half* pA0 = A + (long long)blockIdx.z * sAz
                      + (long long)(blockIdx.y * 128 + lr) * lda + ls * 8;
    const __half* pA1 = pA0 + (long long)64 * lda;
    const __half* pB0 = B + (long long)blockIdx.z * sBz
                      + (long long)(blockIdx.x * TN + lr) * ldb + ls * 8;
    const __half* pB1 = pB0 + (long long)64 * ldb;   // used only if TN==128
    const uint32_t dG0 = swz(lr, ls), dG1 = swz(lr + 64, ls);

    auto load_async = [&](int c, int s) {
        cp16(asb + s * ASTR + dG0, pA0 + c * 32);
        cp16(asb + s * ASTR + dG1, pA1 + c * 32);
        cp16(bsb + s * BSTR + dG0, pB0 + c * 32);
        if (TN == 128) cp16(bsb + s * BSTR + dG1, pB1 + c * 32);
    };

    float acc[2][NJ][4];
#pragma unroll
    for (int i = 0; i < 2; i++)
#pragma unroll
        for (int j = 0; j < NJ; j++)
#pragma unroll
            for (int r = 0; r < 4; r++) acc[i][j][r] = 0.f;

    const int NC = K >> 5;
    load_async(0, 0); cp_commit();
    if (NC > 1) { load_async(1, 1); cp_commit(); }

    int s_cur = 0;
    for (int c = 0; c < NC; ++c) {
        if (c + 1 < NC) cp_wait<1>(); else cp_wait<0>();
        __syncthreads();

        if (c + 2 < NC) {
            int s2 = s_cur + 2; if (s2 >= 3) s2 -= 3;
            load_async(c + 2, s2);
            cp_commit();
        }

        const uint32_t ab = asb + s_cur * ASTR;
        const uint32_t bb = bsb + s_cur * BSTR;
#pragma unroll
        for (int ks = 0; ks < 2; ++ks) {
            uint32_t af[2][4], bf[NP][4];
#pragma unroll
            for (int mt = 0; mt < 2; ++mt) {
                int r = wm * 32 + mt * 16 + (lane & 15);
                int s = 2 * ks + (lane >> 4);
                ldsm4(af[mt], ab + swz(r, s));
            }
#pragma unroll
            for (int p = 0; p < NP; ++p) {
                int r = wn * (TN / 2) + p * 16 + ((lane >> 4) << 3) + (lane & 7);
                int s = 2 * ks + ((lane >> 3) & 1);
                ldsm4(bf[p], bb + swz(r, s));
            }
#pragma unroll
            for (int mt = 0; mt < 2; ++mt)
#pragma unroll
                for (int j = 0; j < NJ; ++j)
                    mma_f16(acc[mt][j], af[mt], bf[j >> 1][2 * (j & 1)],
                            bf[j >> 1][2 * (j & 1) + 1]);
        }

        ++s_cur; if (s_cur == 3) s_cur = 0;
        __syncthreads();
    }

    // ---- epilogue ----
    const long long zC = (long long)blockIdx.z * sCz;
#pragma unroll
    for (int mt = 0; mt < 2; ++mt) {
        int row0 = blockIdx.y * 128 + wm * 32 + mt * 16 + grp;
#pragma unroll
        for (int j = 0; j < NJ; ++j) {
            int col = blockIdx.x * TN + wn * (TN / 2) + j * 8 + 2 * qid;
            if (EPI == 0) {
                float b0 = HB ? bias[col] : 0.f;
                float b1 = HB ? bias[col + 1] : 0.f;
                *(float2*)&C[(long long)row0 * ldc + col + zC] =
                    make_float2(alpha * acc[mt][j][0] + b0, alpha * acc[mt][j][1] + b1);
                *(float2*)&C[(long long)(row0 + 8) * ldc + col + zC] =
                    make_float2(alpha * acc[mt][j][2] + b0, alpha * acc[mt][j][3] + b1);
            } else {
                __half2 v0 = __floats2half2_rn(alpha * acc[mt][j][0], alpha * acc[mt][j][1]);
                __half2 v1 = __floats2half2_rn(alpha * acc[mt][j][2], alpha * acc[mt][j][3]);
                *(__half2*)&Cf[(long long)row0 * ldc + col + zC] = v0;
                *(__half2*)&Cf[(long long)(row0 + 8) * ldc + col + zC] = v1;
            }
        }
    }
}

// ---------------------------------------------------------------------------
// Batched fp32 -> fp16 convert: blockIdx.y selects tensor
// ---------------------------------------------------------------------------
__global__ void cvt_h3(const float* __restrict__ a, const float* __restrict__ b,
                       const float* __restrict__ c,
                       __half* __restrict__ A, __half* __restrict__ B,
                       __half* __restrict__ C, int n4)
{
    int idx = blockIdx.x * blockDim.x + threadIdx.x;
    if (idx >= n4) return;
    const float* src = (blockIdx.y == 0) ? a : (blockIdx.y == 1) ? b : c;
    __half* dst = (blockIdx.y == 0) ? A : (blockIdx.y == 1) ? B : C;
    float4 x = ((const float4*)src)[idx];
    __half2 u = __floats2half2_rn(x.x, x.y);
    __half2 v = __floats2half2_rn(x.z, x.w);
    *(uint2*)(dst + 4 * (size_t)idx) = make_uint2(*(uint32_t*)&u, *(uint32_t*)&v);
}

__global__ void cvt_h4(const float* __restrict__ a, const float* __restrict__ b,
                       const float* __restrict__ c, const float* __restrict__ d,
                       __half* __restrict__ A, __half* __restrict__ B,
                       __half* __restrict__ C, __half* __restrict__ D, int n4)
{
    int idx = blockIdx.x * blockDim.x + threadIdx.x;
    if (idx >= n4) return;
    const float* src = (blockIdx.y == 0) ? a : (blockIdx.y == 1) ? b
                     : (blockIdx.y == 2) ? c : d;
    __half* dst = (blockIdx.y == 0) ? A : (blockIdx.y == 1) ? B
                : (blockIdx.y == 2) ? C : D;
    float4 x = ((const float4*)src)[idx];
    __half2 u = __floats2half2_rn(x.x, x.y);
    __half2 v = __floats2half2_rn(x.z, x.w);
    *(uint2*)(dst + 4 * (size_t)idx) = make_uint2(*(uint32_t*)&u, *(uint32_t*)&v);
}

// ---------------------------------------------------------------------------
// RoPE: fp32 Q/K -> rotated fp16 planes
// ---------------------------------------------------------------------------
__global__ void rope_h(const float* __restrict__ Q, const float* __restrict__ K,
                       __half* __restrict__ Qh, __half* __restrict__ Kh)
{
    int tid = blockIdx.x * blockDim.x + threadIdx.x;
    if (tid >= SEQ * NH * 32) return;
    int i = tid & 31;
    int h = (tid >> 5) & (NH - 1);
    int s = tid >> 9;

    float inv_freq = expf(-0.28782313662425576f * (float)i);
    float angle = (float)s * inv_freq;
    float sn, cs;
    sincosf(angle, &sn, &cs);

    long long base = (long long)s * DM + h * DK + i;
    float q1 = Q[base], q2 = Q[base + 32];
    Qh[base]      = __float2half_rn(q1 * cs - q2 * sn);
    Qh[base + 32] = __float2half_rn(q2 * cs + q1 * sn);
    float k1 = K[base], k2 = K[base + 32];
    Kh[base]      = __float2half_rn(k1 * cs - k2 * sn);
    Kh[base + 32] = __float2half_rn(k2 * cs + k1 * sn);
}

// ---------------------------------------------------------------------------
// V transpose: fp32 V[s, h*64+d] -> fp16 Vt[h][d][s]
// ---------------------------------------------------------------------------
__global__ void vtrans_h(const float* __restrict__ V, __half* __restrict__ T)
{
    __shared__ float tile[32][33];
    int c0 = blockIdx.x * 32, s0 = blockIdx.y * 32;
    int tx = threadIdx.x, ty = threadIdx.y;   // 32 x 8
#pragma unroll
    for (int k = 0; k < 4; ++k)
        tile[ty + 8 * k][tx] = V[(long long)(s0 + ty + 8 * k) * DM + c0 + tx];
    __syncthreads();
#pragma unroll
    for (int k = 0; k < 4; ++k) {
        int c = c0 + ty + 8 * k;
        int s = s0 + tx;
        long long o = (long long)(c >> 6) * DK * SEQ + (long long)(c & 63) * SEQ + s;
        T[o] = __float2half_rn(tile[tx][ty + 8 * k]);
    }
}

// ---------------------------------------------------------------------------
// Softmax: read fp16 scores from P, write fp32 probs to attn and fp16 to P.
// ---------------------------------------------------------------------------
__global__ __launch_bounds__(256)
void softmax_h(__half* __restrict__ P, float* __restrict__ attn)
{
    const long long rbase = (long long)blockIdx.x * 2048;
    __half* p = P + rbase;
    float* a = attn + rbase;
    const int t = threadIdx.x;
    const int lane = t & 31, w = t >> 5;

    uint4 raw = *(const uint4*)(p + 8 * t);
    float v[8];
    {
        float2 f0 = __half22float2(*(__half2*)&raw.x);
        float2 f1 = __half22float2(*(__half2*)&raw.y);
        float2 f2 = __half22float2(*(__half2*)&raw.z);
        float2 f3 = __half22float2(*(__half2*)&raw.w);
        v[0] = f0.x; v[1] = f0.y; v[2] = f1.x; v[3] = f1.y;
        v[4] = f2.x; v[5] = f2.y; v[6] = f3.x; v[7] = f3.y;
    }

    float m = v[0];
#pragma unroll
    for (int j = 1; j < 8; j++) m = fmaxf(m, v[j]);

    __shared__ float shm[8], shs[8];
#pragma unroll
    for (int o = 16; o; o >>= 1) m = fmaxf(m, __shfl_xor_sync(0xffffffffu, m, o));
    if (lane == 0) shm[w] = m;
    __syncthreads();
    float mm = shm[0];
#pragma unroll
    for (int i = 1; i < 8; i++) mm = fmaxf(mm, shm[i]);

    float sum = 0.f;
#pragma unroll
    for (int j = 0; j < 8; j++) { v[j] = expf(v[j] - mm); sum += v[j]; }
#pragma unroll
    for (int o = 16; o; o >>= 1) sum += __shfl_xor_sync(0xffffffffu, sum, o);
    if (lane == 0) shs[w] = sum;
    __syncthreads();
    float tot = 0.f;
#pragma unroll
    for (int i = 0; i < 8; i++) tot += shs[i];
    float inv = 1.0f / tot;

    float r[8];
#pragma unroll
    for (int j = 0; j < 8; j++) r[j] = v[j] * inv;

    *(float4*)(a + 8 * t)     = make_float4(r[0], r[1], r[2], r[3]);
    *(float4*)(a + 8 * t + 4) = make_float4(r[4], r[5], r[6], r[7]);
    __half2 h0 = __floats2half2_rn(r[0], r[1]);
    __half2 h1 = __floats2half2_rn(r[2], r[3]);
    __half2 h2 = __floats2half2_rn(r[4], r[5]);
    __half2 h3 = __floats2half2_rn(r[6], r[7]);
    *(uint4*)(p + 8 * t) = make_uint4(*(uint32_t*)&h0, *(uint32_t*)&h1,
                                      *(uint32_t*)&h2, *(uint32_t*)&h3);
}

// ---------------------------------------------------------------------------
extern "C" void kernel_launch(void* const* d_in, const int* in_sizes, int n_in,
                              void* d_out, int out_size)
{
    const float* q  = (const float*)d_in[0];
    const float* k  = (const float*)d_in[1];
    const float* v  = (const float*)d_in[2];
    const float* wq = (const float*)d_in[3];
    const float* wk = (const float*)d_in[4];
    const float* wv = (const float*)d_in[5];
    const float* wo = (const float*)d_in[6];
    const float* bo = (const float*)d_in[7];

    float* out  = (float*)d_out;              // [2048, 1024]
    float* attn = out + (size_t)SEQ * DM;     // [16, 2048, 2048]

    float *pQ, *pK, *pV;
    cudaGetSymbolAddress((void**)&pQ, g_Q);
    cudaGetSymbolAddress((void**)&pK, g_K);
    cudaGetSymbolAddress((void**)&pV, g_V);

    __half *xq,*xk,*xv,*hwq,*hwk,*hwv,*hwo,*Qh,*Kh,*Vt,*P,*ctx;
    cudaGetSymbolAddress((void**)&xq, g_xq);
    cudaGetSymbolAddress((void**)&xk, g_xk);
    cudaGetSymbolAddress((void**)&xv, g_xv);
    cudaGetSymbolAddress((void**)&hwq, g_wq);
    cudaGetSymbolAddress((void**)&hwk, g_wk);
    cudaGetSymbolAddress((void**)&hwv, g_wv);
    cudaGetSymbolAddress((void**)&hwo, g_wo);
    cudaGetSymbolAddress((void**)&Qh, g_Qh);
    cudaGetSymbolAddress((void**)&Kh, g_Kh);
    cudaGetSymbolAddress((void**)&Vt, g_Vt);
    cudaGetSymbolAddress((void**)&P, g_P);
    cudaGetSymbolAddress((void**)&ctx, g_ctx);

    const int nIn4 = SEQ * DM / 4, nW4 = DM * DM / 4;

    // 0) fp32 -> fp16 operands (batched)
    cvt_h3<<<dim3(nIn4 / 256, 3), 256>>>(q, k, v, xq, xk, xv, nIn4);
    cvt_h4<<<dim3(nW4 / 256, 4), 256>>>(wq, wk, wv, wo, hwq, hwk, hwv, hwo, nW4);

    // 1) Projections: X @ W^T -> fp32  (128x128 tiles, grid 8x16)
    dim3 gProj(DM / 128, SEQ / 128, 1);
    gemm_h<128, 0, false><<<gProj, 256>>>(xq, hwq, pQ, nullptr, DM, DM, DM, DM, 1.f, nullptr, 0, 0, 0);
    gemm_h<128, 0, false><<<gProj, 256>>>(xk, hwk, pK, nullptr, DM, DM, DM, DM, 1.f, nullptr, 0, 0, 0);
    gemm_h<128, 0, false><<<gProj, 256>>>(xv, hwv, pV, nullptr, DM, DM, DM, DM, 1.f, nullptr, 0, 0, 0);

    // 2) RoPE -> fp16 Q/K ; V transpose -> fp16 Vt
    rope_h<<<(SEQ * NH * 32 + 255) / 256, 256>>>(pQ, pK, Qh, Kh);
    vtrans_h<<<dim3(DM / 32, SEQ / 32), dim3(32, 8)>>>(pV, Vt);

    // 3) Scores -> fp16 P = (Q_h @ K_h^T) / 8  (128x128 tiles, grid 16x16x16)
    dim3 gScore(SEQ / 128, SEQ / 128, NH);
    gemm_h<128, 1, false><<<gScore, 256>>>(Qh, Kh, nullptr, P, DK, DM, DM, SEQ, 0.125f,
                                           nullptr, DK, DK, (long long)SEQ * SEQ);

    // 4) Softmax: P fp16 -> attn fp32 + P fp16 (probs)
    softmax_h<<<NH * SEQ, 256>>>(P, attn);

    // 5) ctx_h = P_h @ Vt_h^T  (M=2048, N=64, K=2048) -> fp16 ctx
    dim3 gAV(1, SEQ / 128, NH);
    gemm_h<64, 1, false><<<gAV, 256>>>(P, Vt, nullptr, ctx, SEQ, SEQ, SEQ, DM, 1.f,
                                       nullptr, (long long)SEQ * SEQ, (long long)DK * SEQ, DK);

    // 6) out = ctx @ w_o^T + b_o  (128x128 tiles)
    dim3 gOut(DM / 128, SEQ / 128, 1);
    gemm_h<128, 0, true><<<gOut, 256>>>(ctx, hwo, out, nullptr, DM, DM, DM, DM, 1.f, bo, 0, 0, 0);
}

// round 11
// speedup vs baseline: 2.5018x; 1.0434x over previous
#include <cuda_runtime.h>
#include <cuda_fp16.h>
#include <cstdint>
#include <math.h>

#define SEQ 2048
#define DM  1024
#define NH  16
#define DK  64

// ---------------- scratch (device globals; no allocation allowed) ----------
__device__ float g_Q[SEQ * DM];
__device__ float g_K[SEQ * DM];
__device__ float g_V[SEQ * DM];
__device__ float g_inv[NH * SEQ];
__device__ __half g_xq[SEQ * DM], g_xk[SEQ * DM], g_xv[SEQ * DM];
__device__ __half g_wq[DM * DM], g_wk[DM * DM], g_wv[DM * DM], g_wo[DM * DM];
__device__ __half g_Qh[SEQ * DM], g_Kh[SEQ * DM];
__device__ __half g_Vt[NH * DK * SEQ];
__device__ __half g_P[(size_t)NH * SEQ * SEQ];   // fp16 scores
__device__ __half g_ctx[SEQ * DM];

#define L2E 1.442695041f

// ---------------------------------------------------------------------------
__device__ __forceinline__ void ldsm4(uint32_t* r, uint32_t a) {
    asm volatile("ldmatrix.sync.aligned.m8n8.x4.shared.b16 {%0,%1,%2,%3}, [%4];"
        : "=r"(r[0]), "=r"(r[1]), "=r"(r[2]), "=r"(r[3]) : "r"(a));
}
__device__ __forceinline__ void mma_f16(float* c, const uint32_t* a,
                                        uint32_t b0, uint32_t b1) {
    asm volatile("mma.sync.aligned.m16n8k16.row.col.f32.f16.f16.f32 "
        "{%0,%1,%2,%3},{%4,%5,%6,%7},{%8,%9},{%0,%1,%2,%3};"
        : "+f"(c[0]), "+f"(c[1]), "+f"(c[2]), "+f"(c[3])
        : "r"(a[0]), "r"(a[1]), "r"(a[2]), "r"(a[3]), "r"(b0), "r"(b1));
}
__device__ __forceinline__ void cp16(uint32_t dst, const void* src) {
    asm volatile("cp.async.cg.shared.global [%0], [%1], 16;" :: "r"(dst), "l"(src));
}
__device__ __forceinline__ void cp_commit() {
    asm volatile("cp.async.commit_group;");
}
template<int N> __device__ __forceinline__ void cp_wait() {
    asm volatile("cp.async.wait_group %0;" :: "n"(N));
}
__device__ __forceinline__ uint32_t swz(int r, int s) {
    return (uint32_t)((r * 4 + ((s + (r >> 1)) & 3)) << 4);
}

// ---------------------------------------------------------------------------
// fp16 NT GEMM body. Block tile 128 x TN (64|128), 8 warps (4M x 2N), BK=32,
// 3-stage cp.async. EPI=0: fp32 C (+bias). EPI=1: fp16 Cf (alpha applied).
// ---------------------------------------------------------------------------
template<int TN, int EPI, bool HB>
__device__ __forceinline__ void gemm_body(
    const __half* __restrict__ A, const __half* __restrict__ B,
    float* __restrict__ C, __half* __restrict__ Cf,
    int K, int lda, int ldb, int ldc, float alpha,
    const float* __restrict__ bias, int bx, int by)
{
    constexpr int NP = TN / 32;
    constexpr int NJ = TN / 16;
    __shared__ __align__(16) __half As[3][128 * 32];
    __shared__ __align__(16) __half Bs[3][TN * 32];
    constexpr uint32_t ASTR = 128 * 32 * 2, BSTR = TN * 32 * 2;

    const int t = threadIdx.x, lane = t & 31, w = t >> 5;
    const int wm = w & 3, wn = w >> 2;
    const int grp = lane >> 2, qid = lane & 3;

    const uint32_t asb = (uint32_t)__cvta_generic_to_shared(&As[0][0]);
    const uint32_t bsb = (uint32_t)__cvta_generic_to_shared(&Bs[0][0]);

    const int lr = t >> 2, ls = t & 3;
    const __half* pA0 = A + (long long)(by * 128 + lr) * lda + ls * 8;
    const __half* pA1 = pA0 + (long long)64 * lda;
    const __half* pB0 = B + (long long)(bx * TN + lr) * ldb + ls * 8;
    const __half* pB1 = pB0 + (long long)64 * ldb;
    const uint32_t dG0 = swz(lr, ls), dG1 = swz(lr + 64, ls);

    auto load_async = [&](int c, int s) {
        cp16(asb + s * ASTR + dG0, pA0 + c * 32);
        cp16(asb + s * ASTR + dG1, pA1 + c * 32);
        cp16(bsb + s * BSTR + dG0, pB0 + c * 32);
        if (TN == 128) cp16(bsb + s * BSTR + dG1, pB1 + c * 32);
    };

    float acc[2][NJ][4];
#pragma unroll
    for (int i = 0; i < 2; i++)
#pragma unroll
        for (int j = 0; j < NJ; j++)
#pragma unroll
            for (int r = 0; r < 4; r++) acc[i][j][r] = 0.f;

    const int NC = K >> 5;
    load_async(0, 0); cp_commit();
    if (NC > 1) { load_async(1, 1); cp_commit(); }

    int s_cur = 0;
    for (int c = 0; c < NC; ++c) {
        if (c + 1 < NC) cp_wait<1>(); else cp_wait<0>();
        __syncthreads();

        if (c + 2 < NC) {
            int s2 = s_cur + 2; if (s2 >= 3) s2 -= 3;
            load_async(c + 2, s2);
            cp_commit();
        }

        const uint32_t ab = asb + s_cur * ASTR;
        const uint32_t bb = bsb + s_cur * BSTR;
#pragma unroll
        for (int ks = 0; ks < 2; ++ks) {
            uint32_t af[2][4], bf[NP][4];
#pragma unroll
            for (int mt = 0; mt < 2; ++mt) {
                int r = wm * 32 + mt * 16 + (lane & 15);
                int s = 2 * ks + (lane >> 4);
                ldsm4(af[mt], ab + swz(r, s));
            }
#pragma unroll
            for (int p = 0; p < NP; ++p) {
                int r = wn * (TN / 2) + p * 16 + ((lane >> 4) << 3) + (lane & 7);
                int s = 2 * ks + ((lane >> 3) & 1);
                ldsm4(bf[p], bb + swz(r, s));
            }
#pragma unroll
            for (int mt = 0; mt < 2; ++mt)
#pragma unroll
                for (int j = 0; j < NJ; ++j)
                    mma_f16(acc[mt][j], af[mt], bf[j >> 1][2 * (j & 1)],
                            bf[j >> 1][2 * (j & 1) + 1]);
        }

        ++s_cur; if (s_cur == 3) s_cur = 0;
        __syncthreads();
    }

#pragma unroll
    for (int mt = 0; mt < 2; ++mt) {
        int row0 = by * 128 + wm * 32 + mt * 16 + grp;
#pragma unroll
        for (int j = 0; j < NJ; ++j) {
            int col = bx * TN + wn * (TN / 2) + j * 8 + 2 * qid;
            if (EPI == 0) {
                float b0 = HB ? bias[col] : 0.f;
                float b1 = HB ? bias[col + 1] : 0.f;
                *(float2*)&C[(long long)row0 * ldc + col] =
                    make_float2(alpha * acc[mt][j][0] + b0, alpha * acc[mt][j][1] + b1);
                *(float2*)&C[(long long)(row0 + 8) * ldc + col] =
                    make_float2(alpha * acc[mt][j][2] + b0, alpha * acc[mt][j][3] + b1);
            } else {
                __half2 v0 = __floats2half2_rn(alpha * acc[mt][j][0], alpha * acc[mt][j][1]);
                __half2 v1 = __floats2half2_rn(alpha * acc[mt][j][2], alpha * acc[mt][j][3]);
                *(__half2*)&Cf[(long long)row0 * ldc + col] = v0;
                *(__half2*)&Cf[(long long)(row0 + 8) * ldc + col] = v1;
            }
        }
    }
}

template<int TN, int EPI, bool HB>
__global__ __launch_bounds__(256)
void gemm_h(const __half* __restrict__ A, const __half* __restrict__ B,
            float* __restrict__ C, __half* __restrict__ Cf,
            int K, int lda, int ldb, int ldc, float alpha,
            const float* __restrict__ bias,
            long long sAz, long long sBz, long long sCz)
{
    const __half* Az = A + (long long)blockIdx.z * sAz;
    const __half* Bz = B + (long long)blockIdx.z * sBz;
    float* Cz = C; __half* Cfz = Cf;
    if (EPI == 0) { if (C)  Cz  = C  + (long long)blockIdx.z * sCz; }
    else          { if (Cf) Cfz = Cf + (long long)blockIdx.z * sCz; }
    gemm_body<TN, EPI, HB>(Az, Bz, Cz, Cfz, K, lda, ldb, ldc, alpha, bias,
                           blockIdx.x, blockIdx.y);
}

// Fused QKV projection: blockIdx.z selects (input, weight, output)
__global__ __launch_bounds__(256)
void gemm_qkv(const __half* __restrict__ xq, const __half* __restrict__ xk,
              const __half* __restrict__ xv,
              const __half* __restrict__ wq, const __half* __restrict__ wk,
              const __half* __restrict__ wv,
              float* __restrict__ Q, float* __restrict__ Ko, float* __restrict__ V)
{
    const __half* A = (blockIdx.z == 0) ? xq : (blockIdx.z == 1) ? xk : xv;
    const __half* B = (blockIdx.z == 0) ? wq : (blockIdx.z == 1) ? wk : wv;
    float* C = (blockIdx.z == 0) ? Q : (blockIdx.z == 1) ? Ko : V;
    gemm_body<128, 0, false>(A, B, C, nullptr, DM, DM, DM, DM, 1.f, nullptr,
                             blockIdx.x, blockIdx.y);
}

// ---------------------------------------------------------------------------
// Row stats: inv[row] = 1 / sum_j exp(P[row][j]).  One warp per row.
// ---------------------------------------------------------------------------
__global__ __launch_bounds__(256)
void rowstats(const __half* __restrict__ P, float* __restrict__ inv)
{
    const int row = blockIdx.x * 8 + (threadIdx.x >> 5);
    const int lane = threadIdx.x & 31;
    const __half* p = P + (long long)row * 2048;
    float s = 0.f;
#pragma unroll
    for (int k = 0; k < 8; ++k) {
        uint4 raw = *(const uint4*)(p + k * 256 + lane * 8);
        const __half2* hp = (const __half2*)&raw;
#pragma unroll
        for (int j = 0; j < 4; ++j) {
            float2 f = __half22float2(hp[j]);
            s += exp2f(f.x * L2E) + exp2f(f.y * L2E);
        }
    }
#pragma unroll
    for (int o = 16; o; o >>= 1) s += __shfl_xor_sync(0xffffffffu, s, o);
    if (lane == 0) inv[row] = 1.f / s;
}

// ---------------------------------------------------------------------------
// Fused softmax + AV GEMM. Per CTA: head z, 128 P-rows. Streams K=2048 in
// chunks of 32: probs = exp2(s*log2e + log2(inv)) computed in registers,
// written to fp32 attn and staged to smem as fp16 mma A-operand.
// B = Vt[h][64][2048] via 3-stage cp.async. Output ctx fp16 [128][64].
// ---------------------------------------------------------------------------
__global__ __launch_bounds__(256, 2)
void av_fused(const __half* __restrict__ P, const __half* __restrict__ Vt,
              const float* __restrict__ inv, float* __restrict__ attn,
              __half* __restrict__ ctx)
{
    __shared__ __align__(16) __half Ps[2][128 * 32];
    __shared__ __align__(16) __half Vs[3][64 * 32];
    constexpr uint32_t PSTR = 128 * 32 * 2, VSTR = 64 * 32 * 2;

    const int t = threadIdx.x, lane = t & 31, w = t >> 5;
    const int wm = w & 3, wn = w >> 2, grp = lane >> 2, qid = lane & 3;
    const int h = blockIdx.z, rb = blockIdx.y;

    // per-thread P row (r) and 16-col half (hf)
    const int r = t >> 1, hf = t & 1;
    const long long prow = (long long)h * SEQ * SEQ
                         + (long long)(rb * 128 + r) * SEQ + hf * 16;
    const __half* pS = P + prow;
    float* pA = attn + prow;
    const float l2i = log2f(inv[h * SEQ + rb * 128 + r]);

    const int lr = t >> 2, ls = t & 3;
    const __half* pV = Vt + (long long)h * DK * SEQ + (long long)lr * SEQ + ls * 8;
    const uint32_t psb = (uint32_t)__cvta_generic_to_shared(&Ps[0][0]);
    const uint32_t vsb = (uint32_t)__cvta_generic_to_shared(&Vs[0][0]);
    const uint32_t dV = swz(lr, ls);
    const uint32_t dP0 = swz(r, 2 * hf), dP1 = swz(r, 2 * hf + 1);

    float acc[2][4][4];
#pragma unroll
    for (int i = 0; i < 2; i++)
#pragma unroll
        for (int j = 0; j < 4; j++)
#pragma unroll
            for (int x = 0; x < 4; x++) acc[i][j][x] = 0.f;

    uint4 sc0, sc1;
    auto ldS = [&](int c) {
        sc0 = *(const uint4*)(pS + c * 32);
        sc1 = *(const uint4*)(pS + c * 32 + 8);
    };
    auto emit = [&](int c, int buf) {
        float pr[16];
        const __half2* h0 = (const __half2*)&sc0;
        const __half2* h1 = (const __half2*)&sc1;
#pragma unroll
        for (int j = 0; j < 4; ++j) {
            float2 f = __half22float2(h0[j]);
            pr[2 * j]     = exp2f(fmaf(f.x, L2E, l2i));
            pr[2 * j + 1] = exp2f(fmaf(f.y, L2E, l2i));
            float2 g = __half22float2(h1[j]);
            pr[8 + 2 * j]     = exp2f(fmaf(g.x, L2E, l2i));
            pr[8 + 2 * j + 1] = exp2f(fmaf(g.y, L2E, l2i));
        }
        float* ap = pA + c * 32;
        *(float4*)(ap)      = make_float4(pr[0], pr[1], pr[2], pr[3]);
        *(float4*)(ap + 4)  = make_float4(pr[4], pr[5], pr[6], pr[7]);
        *(float4*)(ap + 8)  = make_float4(pr[8], pr[9], pr[10], pr[11]);
        *(float4*)(ap + 12) = make_float4(pr[12], pr[13], pr[14], pr[15]);
        __half2 q[8];
#pragma unroll
        for (int j = 0; j < 8; ++j) q[j] = __floats2half2_rn(pr[2 * j], pr[2 * j + 1]);
        char* base = (char*)&Ps[buf][0];
        *(uint4*)(base + dP0) = *(uint4*)&q[0];
        *(uint4*)(base + dP1) = *(uint4*)&q[4];
    };
    auto cpV = [&](int c, int s) {
        cp16(vsb + s * VSTR + dV, pV + (long long)c * 32);
        cp_commit();
    };

    ldS(0);
    cpV(0, 0); cpV(1, 1);
    emit(0, 0);
    ldS(1);

    for (int c = 0; c < 64; ++c) {
        if (c < 63) cp_wait<1>(); else cp_wait<0>();
        __syncthreads();
        if (c + 2 < 64) cpV(c + 2, (c + 2) % 3);

        const uint32_t pb = psb + (c & 1) * PSTR;
        const uint32_t vb = vsb + (c % 3) * VSTR;
#pragma unroll
        for (int ks = 0; ks < 2; ++ks) {
            uint32_t af[2][4], bf[2][4];
#pragma unroll
            for (int mt = 0; mt < 2; ++mt) {
                int rr = wm * 32 + mt * 16 + (lane & 15);
                int ss = 2 * ks + (lane >> 4);
                ldsm4(af[mt], pb + swz(rr, ss));
            }
#pragma unroll
            for (int p = 0; p < 2; ++p) {
                int rr = wn * 32 + p * 16 + ((lane >> 4) << 3) + (lane & 7);
                int ss = 2 * ks + ((lane >> 3) & 1);
                ldsm4(bf[p], vb + swz(rr, ss));
            }
#pragma unroll
            for (int mt = 0; mt < 2; ++mt)
#pragma unroll
                for (int j = 0; j < 4; ++j)
                    mma_f16(acc[mt][j], af[mt], bf[j >> 1][2 * (j & 1)],
                            bf[j >> 1][2 * (j & 1) + 1]);
        }

        if (c + 1 < 64) {
            emit(c + 1, (c + 1) & 1);
            if (c + 2 < 64) ldS(c + 2);
        }
    }

    // epilogue: ctx fp16
#pragma unroll
    for (int mt = 0; mt < 2; ++mt) {
        int row0 = rb * 128 + wm * 32 + mt * 16 + grp;
#pragma unroll
        for (int j = 0; j < 4; ++j) {
            int col = h * DK + wn * 32 + j * 8 + 2 * qid;
            __half2 v0 = __floats2half2_rn(acc[mt][j][0], acc[mt][j][1]);
            __half2 v1 = __floats2half2_rn(acc[mt][j][2], acc[mt][j][3]);
            *(__half2*)&ctx[(long long)row0 * DM + col] = v0;
            *(__half2*)&ctx[(long long)(row0 + 8) * DM + col] = v1;
        }
    }
}

// ---------------------------------------------------------------------------
__global__ void cvt_h3(const float* __restrict__ a, const float* __restrict__ b,
                       const float* __restrict__ c,
                       __half* __restrict__ A, __half* __restrict__ B,
                       __half* __restrict__ C, int n4)
{
    int idx = blockIdx.x * blockDim.x + threadIdx.x;
    if (idx >= n4) return;
    const float* src = (blockIdx.y == 0) ? a : (blockIdx.y == 1) ? b : c;
    __half* dst = (blockIdx.y == 0) ? A : (blockIdx.y == 1) ? B : C;
    float4 x = ((const float4*)src)[idx];
    __half2 u = __floats2half2_rn(x.x, x.y);
    __half2 v = __floats2half2_rn(x.z, x.w);
    *(uint2*)(dst + 4 * (size_t)idx) = make_uint2(*(uint32_t*)&u, *(uint32_t*)&v);
}

__global__ void cvt_h4(const float* __restrict__ a, const float* __restrict__ b,
                       const float* __restrict__ c, const float* __restrict__ d,
                       __half* __restrict__ A, __half* __restrict__ B,
                       __half* __restrict__ C, __half* __restrict__ D, int n4)
{
    int idx = blockIdx.x * blockDim.x + threadIdx.x;
    if (idx >= n4) return;
    const float* src = (blockIdx.y == 0) ? a : (blockIdx.y == 1) ? b
                     : (blockIdx.y == 2) ? c : d;
    __half* dst = (blockIdx.y == 0) ? A : (blockIdx.y == 1) ? B
                : (blockIdx.y == 2) ? C : D;
    float4 x = ((const float4*)src)[idx];
    __half2 u = __floats2half2_rn(x.x, x.y);
    __half2 v = __floats2half2_rn(x.z, x.w);
    *(uint2*)(dst + 4 * (size_t)idx) = make_uint2(*(uint32_t*)&u, *(uint32_t*)&v);
}

// ---------------------------------------------------------------------------
__global__ void rope_h(const float* __restrict__ Q, const float* __restrict__ K,
                       __half* __restrict__ Qh, __half* __restrict__ Kh)
{
    int tid = blockIdx.x * blockDim.x + threadIdx.x;
    if (tid >= SEQ * NH * 32) return;
    int i = tid & 31;
    int h = (tid >> 5) & (NH - 1);
    int s = tid >> 9;

    float inv_freq = expf(-0.28782313662425576f * (float)i);
    float angle = (float)s * inv_freq;
    float sn, cs;
    sincosf(angle, &sn, &cs);

    long long base = (long long)s * DM + h * DK + i;
    float q1 = Q[base], q2 = Q[base + 32];
    Qh[base]      = __float2half_rn(q1 * cs - q2 * sn);
    Qh[base + 32] = __float2half_rn(q2 * cs + q1 * sn);
    float k1 = K[base], k2 = K[base + 32];
    Kh[base]      = __float2half_rn(k1 * cs - k2 * sn);
    Kh[base + 32] = __float2half_rn(k2 * cs + k1 * sn);
}

// ---------------------------------------------------------------------------
__global__ void vtrans_h(const float* __restrict__ V, __half* __restrict__ T)
{
    __shared__ float tile[32][33];
    int c0 = blockIdx.x * 32, s0 = blockIdx.y * 32;
    int tx = threadIdx.x, ty = threadIdx.y;   // 32 x 8
#pragma unroll
    for (int k = 0; k < 4; ++k)
        tile[ty + 8 * k][tx] = V[(long long)(s0 + ty + 8 * k) * DM + c0 + tx];
    __syncthreads();
#pragma unroll
    for (int k = 0; k < 4; ++k) {
        int c = c0 + ty + 8 * k;
        int s = s0 + tx;
        long long o = (long long)(c >> 6) * DK * SEQ + (long long)(c & 63) * SEQ + s;
        T[o] = __float2half_rn(tile[tx][ty + 8 * k]);
    }
}

// ---------------------------------------------------------------------------
extern "C" void kernel_launch(void* const* d_in, const int* in_sizes, int n_in,
                              void* d_out, int out_size)
{
    const float* q  = (const float*)d_in[0];
    const float* k  = (const float*)d_in[1];
    const float* v  = (const float*)d_in[2];
    const float* wq = (const float*)d_in[3];
    const float* wk = (const float*)d_in[4];
    const float* wv = (const float*)d_in[5];
    const float* wo = (const float*)d_in[6];
    const float* bo = (const float*)d_in[7];

    float* out  = (float*)d_out;              // [2048, 1024]
    float* attn = out + (size_t)SEQ * DM;     // [16, 2048, 2048]

    float *pQ, *pK, *pV, *pInv;
    cudaGetSymbolAddress((void**)&pQ, g_Q);
    cudaGetSymbolAddress((void**)&pK, g_K);
    cudaGetSymbolAddress((void**)&pV, g_V);
    cudaGetSymbolAddress((void**)&pInv, g_inv);

    __half *xq,*xk,*xv,*hwq,*hwk,*hwv,*hwo,*Qh,*Kh,*Vt,*P,*ctx;
    cudaGetSymbolAddress((void**)&xq, g_xq);
    cudaGetSymbolAddress((void**)&xk, g_xk);
    cudaGetSymbolAddress((void**)&xv, g_xv);
    cudaGetSymbolAddress((void**)&hwq, g_wq);
    cudaGetSymbolAddress((void**)&hwk, g_wk);
    cudaGetSymbolAddress((void**)&hwv, g_wv);
    cudaGetSymbolAddress((void**)&hwo, g_wo);
    cudaGetSymbolAddress((void**)&Qh, g_Qh);
    cudaGetSymbolAddress((void**)&Kh, g_Kh);
    cudaGetSymbolAddress((void**)&Vt, g_Vt);
    cudaGetSymbolAddress((void**)&P, g_P);
    cudaGetSymbolAddress((void**)&ctx, g_ctx);

    const int nIn4 = SEQ * DM / 4, nW4 = DM * DM / 4;

    // 0) fp32 -> fp16 operands (batched)
    cvt_h3<<<dim3(nIn4 / 256, 3), 256>>>(q, k, v, xq, xk, xv, nIn4);
    cvt_h4<<<dim3(nW4 / 256, 4), 256>>>(wq, wk, wv, wo, hwq, hwk, hwv, hwo, nW4);

    // 1) Fused QKV projections (one launch, 384 CTAs)
    gemm_qkv<<<dim3(DM / 128, SEQ / 128, 3), 256>>>(xq, xk, xv, hwq, hwk, hwv,
                                                    pQ, pK, pV);

    // 2) RoPE -> fp16 Q/K ; V transpose -> fp16 Vt
    rope_h<<<(SEQ * NH * 32 + 255) / 256, 256>>>(pQ, pK, Qh, Kh);
    vtrans_h<<<dim3(DM / 32, SEQ / 32), dim3(32, 8)>>>(pV, Vt);

    // 3) Scores -> fp16 P = (Q_h @ K_h^T) / 8
    dim3 gScore(SEQ / 128, SEQ / 128, NH);
    gemm_h<128, 1, false><<<gScore, 256>>>(Qh, Kh, nullptr, P, DK, DM, DM, SEQ, 0.125f,
                                           nullptr, DK, DK, (long long)SEQ * SEQ);

    // 4) Row sums of exp(scores)
    rowstats<<<NH * SEQ / 8, 256>>>(P, pInv);

    // 5) Fused softmax + AV: writes fp32 attn + fp16 ctx
    av_fused<<<dim3(1, SEQ / 128, NH), 256>>>(P, Vt, pInv, attn, ctx);

    // 6) out = ctx @ w_o^T + b_o
    dim3 gOut(DM / 128, SEQ / 128, 1);
    gemm_h<128, 0, true><<<gOut, 256>>>(ctx, hwo, out, nullptr, DM, DM, DM, DM, 1.f, bo, 0, 0, 0);
}

// round 12
// speedup vs baseline: 2.6333x; 1.0526x over previous
#include <cuda_runtime.h>
#include <cuda_fp16.h>
#include <cstdint>
#include <math.h>

#define SEQ 2048
#define DM  1024
#define NH  16
#define DK  64

// ---------------- scratch (device globals; no allocation allowed) ----------
__device__ float g_Q[SEQ * DM];
__device__ float g_K[SEQ * DM];
__device__ float g_V[SEQ * DM];
__device__ float g_sums[NH * SEQ];
__device__ __half g_xq[SEQ * DM], g_xk[SEQ * DM], g_xv[SEQ * DM];
__device__ __half g_wq[DM * DM], g_wk[DM * DM], g_wv[DM * DM], g_wo[DM * DM];
__device__ __half g_Qh[SEQ * DM], g_Kh[SEQ * DM];
__device__ __half g_Vt[NH * DK * SEQ];
__device__ __half g_P[(size_t)NH * SEQ * SEQ];   // fp16 scores
__device__ __half g_ctx[SEQ * DM];

#define L2E 1.442695041f

// ---------------------------------------------------------------------------
__device__ __forceinline__ void ldsm4(uint32_t* r, uint32_t a) {
    asm volatile("ldmatrix.sync.aligned.m8n8.x4.shared.b16 {%0,%1,%2,%3}, [%4];"
        : "=r"(r[0]), "=r"(r[1]), "=r"(r[2]), "=r"(r[3]) : "r"(a));
}
__device__ __forceinline__ void mma_f16(float* c, const uint32_t* a,
                                        uint32_t b0, uint32_t b1) {
    asm volatile("mma.sync.aligned.m16n8k16.row.col.f32.f16.f16.f32 "
        "{%0,%1,%2,%3},{%4,%5,%6,%7},{%8,%9},{%0,%1,%2,%3};"
        : "+f"(c[0]), "+f"(c[1]), "+f"(c[2]), "+f"(c[3])
        : "r"(a[0]), "r"(a[1]), "r"(a[2]), "r"(a[3]), "r"(b0), "r"(b1));
}
__device__ __forceinline__ void cp16(uint32_t dst, const void* src) {
    asm volatile("cp.async.cg.shared.global [%0], [%1], 16;" :: "r"(dst), "l"(src));
}
__device__ __forceinline__ void cp_commit() {
    asm volatile("cp.async.commit_group;");
}
template<int N> __device__ __forceinline__ void cp_wait() {
    asm volatile("cp.async.wait_group %0;" :: "n"(N));
}
__device__ __forceinline__ uint32_t swz(int r, int s) {
    return (uint32_t)((r * 4 + ((s + (r >> 1)) & 3)) << 4);
}

// ---------------------------------------------------------------------------
// fp16 NT GEMM body. Block tile 128 x TN (64|128), 8 warps (4M x 2N), BK=32,
// 3-stage cp.async.
// EPI=0: fp32 C (+bias). EPI=1: fp16 Cf (alpha applied);
// SUMS: additionally atomicAdd per-row sums of exp(stored fp16 value).
// ---------------------------------------------------------------------------
template<int TN, int EPI, bool HB, bool SUMS>
__device__ __forceinline__ void gemm_body(
    const __half* __restrict__ A, const __half* __restrict__ B,
    float* __restrict__ C, __half* __restrict__ Cf,
    int K, int lda, int ldb, int ldc, float alpha,
    const float* __restrict__ bias, float* __restrict__ sums,
    int bx, int by)
{
    constexpr int NP = TN / 32;
    constexpr int NJ = TN / 16;
    __shared__ __align__(16) __half As[3][128 * 32];
    __shared__ __align__(16) __half Bs[3][TN * 32];
    constexpr uint32_t ASTR = 128 * 32 * 2, BSTR = TN * 32 * 2;

    const int t = threadIdx.x, lane = t & 31, w = t >> 5;
    const int wm = w & 3, wn = w >> 2;
    const int grp = lane >> 2, qid = lane & 3;

    const uint32_t asb = (uint32_t)__cvta_generic_to_shared(&As[0][0]);
    const uint32_t bsb = (uint32_t)__cvta_generic_to_shared(&Bs[0][0]);

    const int lr = t >> 2, ls = t & 3;
    const __half* pA0 = A + (long long)(by * 128 + lr) * lda + ls * 8;
    const __half* pA1 = pA0 + (long long)64 * lda;
    const __half* pB0 = B + (long long)(bx * TN + lr) * ldb + ls * 8;
    const __half* pB1 = pB0 + (long long)64 * ldb;
    const uint32_t dG0 = swz(lr, ls), dG1 = swz(lr + 64, ls);

    auto load_async = [&](int c, int s) {
        cp16(asb + s * ASTR + dG0, pA0 + c * 32);
        cp16(asb + s * ASTR + dG1, pA1 + c * 32);
        cp16(bsb + s * BSTR + dG0, pB0 + c * 32);
        if (TN == 128) cp16(bsb + s * BSTR + dG1, pB1 + c * 32);
    };

    float acc[2][NJ][4];
#pragma unroll
    for (int i = 0; i < 2; i++)
#pragma unroll
        for (int j = 0; j < NJ; j++)
#pragma unroll
            for (int r = 0; r < 4; r++) acc[i][j][r] = 0.f;

    const int NC = K >> 5;
    load_async(0, 0); cp_commit();
    if (NC > 1) { load_async(1, 1); cp_commit(); }

    int s_cur = 0;
    for (int c = 0; c < NC; ++c) {
        if (c + 1 < NC) cp_wait<1>(); else cp_wait<0>();
        __syncthreads();

        if (c + 2 < NC) {
            int s2 = s_cur + 2; if (s2 >= 3) s2 -= 3;
            load_async(c + 2, s2);
            cp_commit();
        }

        const uint32_t ab = asb + s_cur * ASTR;
        const uint32_t bb = bsb + s_cur * BSTR;
#pragma unroll
        for (int ks = 0; ks < 2; ++ks) {
            uint32_t af[2][4], bf[NP][4];
#pragma unroll
            for (int mt = 0; mt < 2; ++mt) {
                int r = wm * 32 + mt * 16 + (lane & 15);
                int s = 2 * ks + (lane >> 4);
                ldsm4(af[mt], ab + swz(r, s));
            }
#pragma unroll
            for (int p = 0; p < NP; ++p) {
                int r = wn * (TN / 2) + p * 16 + ((lane >> 4) << 3) + (lane & 7);
                int s = 2 * ks + ((lane >> 3) & 1);
                ldsm4(bf[p], bb + swz(r, s));
            }
#pragma unroll
            for (int mt = 0; mt < 2; ++mt)
#pragma unroll
                for (int j = 0; j < NJ; ++j)
                    mma_f16(acc[mt][j], af[mt], bf[j >> 1][2 * (j & 1)],
                            bf[j >> 1][2 * (j & 1) + 1]);
        }

        ++s_cur; if (s_cur == 3) s_cur = 0;
        __syncthreads();
    }

#pragma unroll
    for (int mt = 0; mt < 2; ++mt) {
        int row0 = by * 128 + wm * 32 + mt * 16 + grp;
        float ps0 = 0.f, ps1 = 0.f;
#pragma unroll
        for (int j = 0; j < NJ; ++j) {
            int col = bx * TN + wn * (TN / 2) + j * 8 + 2 * qid;
            if (EPI == 0) {
                float b0 = HB ? bias[col] : 0.f;
                float b1 = HB ? bias[col + 1] : 0.f;
                *(float2*)&C[(long long)row0 * ldc + col] =
                    make_float2(alpha * acc[mt][j][0] + b0, alpha * acc[mt][j][1] + b1);
                *(float2*)&C[(long long)(row0 + 8) * ldc + col] =
                    make_float2(alpha * acc[mt][j][2] + b0, alpha * acc[mt][j][3] + b1);
            } else {
                __half2 v0 = __floats2half2_rn(alpha * acc[mt][j][0], alpha * acc[mt][j][1]);
                __half2 v1 = __floats2half2_rn(alpha * acc[mt][j][2], alpha * acc[mt][j][3]);
                *(__half2*)&Cf[(long long)row0 * ldc + col] = v0;
                *(__half2*)&Cf[(long long)(row0 + 8) * ldc + col] = v1;
                if (SUMS) {
                    float2 f0 = __half22float2(v0);
                    float2 f1 = __half22float2(v1);
                    ps0 += exp2f(f0.x * L2E) + exp2f(f0.y * L2E);
                    ps1 += exp2f(f1.x * L2E) + exp2f(f1.y * L2E);
                }
            }
        }
        if (SUMS) {
            ps0 += __shfl_xor_sync(0xffffffffu, ps0, 1);
            ps0 += __shfl_xor_sync(0xffffffffu, ps0, 2);
            ps1 += __shfl_xor_sync(0xffffffffu, ps1, 1);
            ps1 += __shfl_xor_sync(0xffffffffu, ps1, 2);
            if (qid == 0) {
                atomicAdd(&sums[row0], ps0);
                atomicAdd(&sums[row0 + 8], ps1);
            }
        }
    }
}

template<int TN, int EPI, bool HB, bool SUMS>
__global__ __launch_bounds__(256)
void gemm_h(const __half* __restrict__ A, const __half* __restrict__ B,
            float* __restrict__ C, __half* __restrict__ Cf,
            float* __restrict__ sums,
            int K, int lda, int ldb, int ldc, float alpha,
            const float* __restrict__ bias,
            long long sAz, long long sBz, long long sCz)
{
    const __half* Az = A + (long long)blockIdx.z * sAz;
    const __half* Bz = B + (long long)blockIdx.z * sBz;
    float* Cz = C; __half* Cfz = Cf;
    if (EPI == 0) { if (C)  Cz  = C  + (long long)blockIdx.z * sCz; }
    else          { if (Cf) Cfz = Cf + (long long)blockIdx.z * sCz; }
    float* sz = SUMS ? sums + (long long)blockIdx.z * SEQ : nullptr;
    gemm_body<TN, EPI, HB, SUMS>(Az, Bz, Cz, Cfz, K, lda, ldb, ldc, alpha, bias,
                                 sz, blockIdx.x, blockIdx.y);
}

// Fused QKV projection: blockIdx.z selects (input, weight, output)
__global__ __launch_bounds__(256)
void gemm_qkv(const __half* __restrict__ xq, const __half* __restrict__ xk,
              const __half* __restrict__ xv,
              const __half* __restrict__ wq, const __half* __restrict__ wk,
              const __half* __restrict__ wv,
              float* __restrict__ Q, float* __restrict__ Ko, float* __restrict__ V)
{
    const __half* A = (blockIdx.z == 0) ? xq : (blockIdx.z == 1) ? xk : xv;
    const __half* B = (blockIdx.z == 0) ? wq : (blockIdx.z == 1) ? wk : wv;
    float* C = (blockIdx.z == 0) ? Q : (blockIdx.z == 1) ? Ko : V;
    gemm_body<128, 0, false, false>(A, B, C, nullptr, DM, DM, DM, DM, 1.f,
                                    nullptr, nullptr, blockIdx.x, blockIdx.y);
}

// ---------------------------------------------------------------------------
// Fused softmax + AV GEMM (reads raw row sums).
// ---------------------------------------------------------------------------
__global__ __launch_bounds__(256, 2)
void av_fused(const __half* __restrict__ P, const __half* __restrict__ Vt,
              const float* __restrict__ sums, float* __restrict__ attn,
              __half* __restrict__ ctx)
{
    __shared__ __align__(16) __half Ps[2][128 * 32];
    __shared__ __align__(16) __half Vs[3][64 * 32];
    constexpr uint32_t PSTR = 128 * 32 * 2, VSTR = 64 * 32 * 2;

    const int t = threadIdx.x, lane = t & 31, w = t >> 5;
    const int wm = w & 3, wn = w >> 2, grp = lane >> 2, qid = lane & 3;
    const int h = blockIdx.z, rb = blockIdx.y;

    const int r = t >> 1, hf = t & 1;
    const long long prow = (long long)h * SEQ * SEQ
                         + (long long)(rb * 128 + r) * SEQ + hf * 16;
    const __half* pS = P + prow;
    float* pA = attn + prow;
    const float l2i = -log2f(sums[h * SEQ + rb * 128 + r]);

    const int lr = t >> 2, ls = t & 3;
    const __half* pV = Vt + (long long)h * DK * SEQ + (long long)lr * SEQ + ls * 8;
    const uint32_t psb = (uint32_t)__cvta_generic_to_shared(&Ps[0][0]);
    const uint32_t vsb = (uint32_t)__cvta_generic_to_shared(&Vs[0][0]);
    const uint32_t dV = swz(lr, ls);
    const uint32_t dP0 = swz(r, 2 * hf), dP1 = swz(r, 2 * hf + 1);

    float acc[2][4][4];
#pragma unroll
    for (int i = 0; i < 2; i++)
#pragma unroll
        for (int j = 0; j < 4; j++)
#pragma unroll
            for (int x = 0; x < 4; x++) acc[i][j][x] = 0.f;

    uint4 sc0, sc1;
    auto ldS = [&](int c) {
        sc0 = *(const uint4*)(pS + c * 32);
        sc1 = *(const uint4*)(pS + c * 32 + 8);
    };
    auto emit = [&](int c, int buf) {
        float pr[16];
        const __half2* h0 = (const __half2*)&sc0;
        const __half2* h1 = (const __half2*)&sc1;
#pragma unroll
        for (int j = 0; j < 4; ++j) {
            float2 f = __half22float2(h0[j]);
            pr[2 * j]     = exp2f(fmaf(f.x, L2E, l2i));
            pr[2 * j + 1] = exp2f(fmaf(f.y, L2E, l2i));
            float2 g = __half22float2(h1[j]);
            pr[8 + 2 * j]     = exp2f(fmaf(g.x, L2E, l2i));
            pr[8 + 2 * j + 1] = exp2f(fmaf(g.y, L2E, l2i));
        }
        float* ap = pA + c * 32;
        *(float4*)(ap)      = make_float4(pr[0], pr[1], pr[2], pr[3]);
        *(float4*)(ap + 4)  = make_float4(pr[4], pr[5], pr[6], pr[7]);
        *(float4*)(ap + 8)  = make_float4(pr[8], pr[9], pr[10], pr[11]);
        *(float4*)(ap + 12) = make_float4(pr[12], pr[13], pr[14], pr[15]);
        __half2 q[8];
#pragma unroll
        for (int j = 0; j < 8; ++j) q[j] = __floats2half2_rn(pr[2 * j], pr[2 * j + 1]);
        char* base = (char*)&Ps[buf][0];
        *(uint4*)(base + dP0) = *(uint4*)&q[0];
        *(uint4*)(base + dP1) = *(uint4*)&q[4];
    };
    auto cpV = [&](int c, int s) {
        cp16(vsb + s * VSTR + dV, pV + (long long)c * 32);
        cp_commit();
    };

    ldS(0);
    cpV(0, 0); cpV(1, 1);
    emit(0, 0);
    ldS(1);

    for (int c = 0; c < 64; ++c) {
        if (c < 63) cp_wait<1>(); else cp_wait<0>();
        __syncthreads();
        if (c + 2 < 64) cpV(c + 2, (c + 2) % 3);

        const uint32_t pb = psb + (c & 1) * PSTR;
        const uint32_t vb = vsb + (c % 3) * VSTR;
#pragma unroll
        for (int ks = 0; ks < 2; ++ks) {
            uint32_t af[2][4], bf[2][4];
#pragma unroll
            for (int mt = 0; mt < 2; ++mt) {
                int rr = wm * 32 + mt * 16 + (lane & 15);
                int ss = 2 * ks + (lane >> 4);
                ldsm4(af[mt], pb + swz(rr, ss));
            }
#pragma unroll
            for (int p = 0; p < 2; ++p) {
                int rr = wn * 32 + p * 16 + ((lane >> 4) << 3) + (lane & 7);
                int ss = 2 * ks + ((lane >> 3) & 1);
                ldsm4(bf[p], vb + swz(rr, ss));
            }
#pragma unroll
            for (int mt = 0; mt < 2; ++mt)
#pragma unroll
                for (int j = 0; j < 4; ++j)
                    mma_f16(acc[mt][j], af[mt], bf[j >> 1][2 * (j & 1)],
                            bf[j >> 1][2 * (j & 1) + 1]);
        }

        if (c + 1 < 64) {
            emit(c + 1, (c + 1) & 1);
            if (c + 2 < 64) ldS(c + 2);
        }
    }

#pragma unroll
    for (int mt = 0; mt < 2; ++mt) {
        int row0 = rb * 128 + wm * 32 + mt * 16 + grp;
#pragma unroll
        for (int j = 0; j < 4; ++j) {
            int col = h * DK + wn * 32 + j * 8 + 2 * qid;
            __half2 v0 = __floats2half2_rn(acc[mt][j][0], acc[mt][j][1]);
            __half2 v1 = __floats2half2_rn(acc[mt][j][2], acc[mt][j][3]);
            *(__half2*)&ctx[(long long)row0 * DM + col] = v0;
            *(__half2*)&ctx[(long long)(row0 + 8) * DM + col] = v1;
        }
    }
}

// ---------------------------------------------------------------------------
// Merged fp32 -> fp16 convert for all 7 operand tensors (flattened grid).
// Blocks [0, 6144): inputs q,k,v (2048 blocks each).
// Blocks [6144, 10240): weights wq,wk,wv,wo (1024 blocks each).
// ---------------------------------------------------------------------------
__global__ void cvt_all(const float* __restrict__ q, const float* __restrict__ k,
                        const float* __restrict__ v, const float* __restrict__ wq,
                        const float* __restrict__ wk, const float* __restrict__ wv,
                        const float* __restrict__ wo,
                        __half* __restrict__ xq, __half* __restrict__ xk,
                        __half* __restrict__ xv, __half* __restrict__ hwq,
                        __half* __restrict__ hwk, __half* __restrict__ hwv,
                        __half* __restrict__ hwo)
{
    int b = blockIdx.x;
    const float* src; __half* dst; int idx;
    if (b < 6144) {
        int ti = b >> 11, r = b & 2047;
        src = (ti == 0) ? q : (ti == 1) ? k : v;
        dst = (ti == 0) ? xq : (ti == 1) ? xk : xv;
        idx = r * 256 + threadIdx.x;
    } else {
        int bb = b - 6144;
        int ti = bb >> 10, r = bb & 1023;
        src = (ti == 0) ? wq : (ti == 1) ? wk : (ti == 2) ? wv : wo;
        dst = (ti == 0) ? hwq : (ti == 1) ? hwk : (ti == 2) ? hwv : hwo;
        idx = r * 256 + threadIdx.x;
    }
    float4 x = ((const float4*)src)[idx];
    __half2 u = __floats2half2_rn(x.x, x.y);
    __half2 w2 = __floats2half2_rn(x.z, x.w);
    *(uint2*)(dst + 4 * (size_t)idx) = make_uint2(*(uint32_t*)&u, *(uint32_t*)&w2);
}

// ---------------------------------------------------------------------------
// Merged RoPE (blocks [0,4096)) + V transpose (blocks [4096,6144)).
// ---------------------------------------------------------------------------
__global__ void rope_vtrans(const float* __restrict__ Q, const float* __restrict__ K,
                            const float* __restrict__ V,
                            __half* __restrict__ Qh, __half* __restrict__ Kh,
                            __half* __restrict__ Vt)
{
    if (blockIdx.x < 4096) {
        int tid = blockIdx.x * 256 + threadIdx.x;
        int i = tid & 31;
        int h = (tid >> 5) & (NH - 1);
        int s = tid >> 9;

        float inv_freq = exp2f(-0.41524101186092029f * (float)i); // log2(10000)/32
        float angle = (float)s * inv_freq;
        float sn, cs;
        sincosf(angle, &sn, &cs);

        long long base = (long long)s * DM + h * DK + i;
        float q1 = Q[base], q2 = Q[base + 32];
        Qh[base]      = __float2half_rn(q1 * cs - q2 * sn);
        Qh[base + 32] = __float2half_rn(q2 * cs + q1 * sn);
        float k1 = K[base], k2 = K[base + 32];
        Kh[base]      = __float2half_rn(k1 * cs - k2 * sn);
        Kh[base + 32] = __float2half_rn(k2 * cs + k1 * sn);
    } else {
        __shared__ float tile[32][33];
        int bb = blockIdx.x - 4096;
        int c0 = (bb & 31) * 32, s0 = (bb >> 5) * 32;
        int tx = threadIdx.x & 31, ty = threadIdx.x >> 5;   // 32 x 8
#pragma unroll
        for (int kk = 0; kk < 4; ++kk)
            tile[ty + 8 * kk][tx] = V[(long long)(s0 + ty + 8 * kk) * DM + c0 + tx];
        __syncthreads();
#pragma unroll
        for (int kk = 0; kk < 4; ++kk) {
            int c = c0 + ty + 8 * kk;
            int s = s0 + tx;
            long long o = (long long)(c >> 6) * DK * SEQ + (long long)(c & 63) * SEQ + s;
            Vt[o] = __float2half_rn(tile[tx][ty + 8 * kk]);
        }
    }
}

// ---------------------------------------------------------------------------
extern "C" void kernel_launch(void* const* d_in, const int* in_sizes, int n_in,
                              void* d_out, int out_size)
{
    const float* q  = (const float*)d_in[0];
    const float* k  = (const float*)d_in[1];
    const float* v  = (const float*)d_in[2];
    const float* wq = (const float*)d_in[3];
    const float* wk = (const float*)d_in[4];
    const float* wv = (const float*)d_in[5];
    const float* wo = (const float*)d_in[6];
    const float* bo = (const float*)d_in[7];

    float* out  = (float*)d_out;              // [2048, 1024]
    float* attn = out + (size_t)SEQ * DM;     // [16, 2048, 2048]

    float *pQ, *pK, *pV, *pSums;
    cudaGetSymbolAddress((void**)&pQ, g_Q);
    cudaGetSymbolAddress((void**)&pK, g_K);
    cudaGetSymbolAddress((void**)&pV, g_V);
    cudaGetSymbolAddress((void**)&pSums, g_sums);

    __half *xq,*xk,*xv,*hwq,*hwk,*hwv,*hwo,*Qh,*Kh,*Vt,*P,*ctx;
    cudaGetSymbolAddress((void**)&xq, g_xq);
    cudaGetSymbolAddress((void**)&xk, g_xk);
    cudaGetSymbolAddress((void**)&xv, g_xv);
    cudaGetSymbolAddress((void**)&hwq, g_wq);
    cudaGetSymbolAddress((void**)&hwk, g_wk);
    cudaGetSymbolAddress((void**)&hwv, g_wv);
    cudaGetSymbolAddress((void**)&hwo, g_wo);
    cudaGetSymbolAddress((void**)&Qh, g_Qh);
    cudaGetSymbolAddress((void**)&Kh, g_Kh);
    cudaGetSymbolAddress((void**)&Vt, g_Vt);
    cudaGetSymbolAddress((void**)&P, g_P);
    cudaGetSymbolAddress((void**)&ctx, g_ctx);

    // 0) zero row sums + convert all operands to fp16
    cudaMemsetAsync(pSums, 0, NH * SEQ * sizeof(float));
    cvt_all<<<10240, 256>>>(q, k, v, wq, wk, wv, wo,
                            xq, xk, xv, hwq, hwk, hwv, hwo);

    // 1) Fused QKV projections (one launch, 384 CTAs)
    gemm_qkv<<<dim3(DM / 128, SEQ / 128, 3), 256>>>(xq, xk, xv, hwq, hwk, hwv,
                                                    pQ, pK, pV);

    // 2) RoPE -> fp16 Q/K ; V transpose -> fp16 Vt (one launch)
    rope_vtrans<<<4096 + 2048, 256>>>(pQ, pK, pV, Qh, Kh, Vt);

    // 3) Scores -> fp16 P = (Q_h @ K_h^T) / 8, + exp-row-sums via atomics
    dim3 gScore(SEQ / 128, SEQ / 128, NH);
    gemm_h<128, 1, false, true><<<gScore, 256>>>(Qh, Kh, nullptr, P, pSums,
                                                 DK, DM, DM, SEQ, 0.125f, nullptr,
                                                 DK, DK, (long long)SEQ * SEQ);

    // 4) Fused softmax + AV: writes fp32 attn + fp16 ctx
    av_fused<<<dim3(1, SEQ / 128, NH), 256>>>(P, Vt, pSums, attn, ctx);

    // 5) out = ctx @ w_o^T + b_o
    dim3 gOut(DM / 128, SEQ / 128, 1);
    gemm_h<128, 0, true, false><<<gOut, 256>>>(ctx, hwo, out, nullptr, nullptr,
                                               DM, DM, DM, DM, 1.f, bo, 0, 0, 0);
}